// round 12
// baseline (speedup 1.0000x reference)
#include <cuda_runtime.h>
#include <cuda_fp16.h>
#include <math.h>

#define S 1024
#define D 768
#define LAYERS 12
#define HEADS 24
#define DKV 32
#define QKV_N 2304
#define FF_N 1536
#define VSZ 50304
#define NCH 32
#define CT 32

// ---------------- scratch -----------------------------------------------
__device__ float g_x[S*D];
__device__ float g_h[S*2*D];
__device__ float g_qkv[S*QKV_N];
__device__ float g_Asum[HEADS*NCH*DKV*DKV];
__device__ float g_Zsum[HEADS*NCH*DKV];

__device__ __half g_xh[S*D];
__device__ __half g_xnh[S*D];
__device__ __half g_atth[S*D];
__device__ __half g_gluh[S*D];
__device__ __half g_poswh[D*2*D];
__device__ __half g_qkvwh[LAYERS*D*QKV_N];
__device__ __half g_ff1wh[LAYERS*D*FF_N];
__device__ __half g_ff2wh[LAYERS*D*D];
__device__ __half g_embwh[(size_t)VSZ*D];

// ---------------- low-level helpers --------------------------------------
__device__ __forceinline__ unsigned s2u(const void* p) {
    return (unsigned)__cvta_generic_to_shared(p);
}
__device__ __forceinline__ void cp16(unsigned dst, const void* src) {
    asm volatile("cp.async.cg.shared.global [%0], [%1], 16;\n" :: "r"(dst), "l"(src));
}
__device__ __forceinline__ void cp_commit() {
    asm volatile("cp.async.commit_group;\n");
}
template<int N>
__device__ __forceinline__ void cp_wait() {
    asm volatile("cp.async.wait_group %0;\n" :: "n"(N));
}
__device__ __forceinline__ void ldm4(unsigned* r, const __half* p) {
    unsigned a = s2u(p);
    asm volatile("ldmatrix.sync.aligned.m8n8.x4.shared.b16 {%0,%1,%2,%3}, [%4];"
        : "=r"(r[0]), "=r"(r[1]), "=r"(r[2]), "=r"(r[3]) : "r"(a));
}
__device__ __forceinline__ void mma16816(float* c, const unsigned* a, unsigned b0, unsigned b1) {
    asm volatile(
        "mma.sync.aligned.m16n8k16.row.col.f32.f16.f16.f32 "
        "{%0,%1,%2,%3},{%4,%5,%6,%7},{%8,%9},{%0,%1,%2,%3};"
        : "+f"(c[0]), "+f"(c[1]), "+f"(c[2]), "+f"(c[3])
        : "r"(a[0]), "r"(a[1]), "r"(a[2]), "r"(a[3]), "r"(b0), "r"(b1));
}
// swizzled index (half units) in a [rows][32] k-major half tile
__device__ __forceinline__ int swzh(int r, int k) {
    return r*32 + ((((k >> 3) ^ ((r >> 1) & 3)) << 3) | (k & 7));
}

// ---------------- weight prep: transpose + convert ------------------------
__global__ __launch_bounds__(256) void tconv_k(const float* __restrict__ src,
                                               __half* __restrict__ dst, int R, int Cc)
{
    __shared__ float t[32][33];
    int c0 = blockIdx.x*32, r0 = blockIdx.y*32, z = blockIdx.z;
    src += (size_t)z*R*Cc;
    dst += (size_t)z*R*Cc;
    int tx = threadIdx.x, ty = threadIdx.y;   // 32 x 8
    #pragma unroll
    for (int i = 0; i < 4; i++)
        t[ty + 8*i][tx] = src[(size_t)(r0 + ty + 8*i)*Cc + c0 + tx];
    __syncthreads();
    #pragma unroll
    for (int i = 0; i < 4; i++)
        dst[(size_t)(c0 + ty + 8*i)*R + r0 + tx] = __float2half_rn(t[tx][ty + 8*i]);
}
__global__ __launch_bounds__(256) void conv_k(const float* __restrict__ src,
                                              __half* __restrict__ dst, size_t n2)
{
    size_t stride = (size_t)gridDim.x * blockDim.x;
    for (size_t i = (size_t)blockIdx.x*blockDim.x + threadIdx.x; i < n2; i += stride) {
        float2 v = ((const float2*)src)[i];
        ((__half2*)dst)[i] = __floats2half2_rn(v.x, v.y);
    }
}

// ---------------- embedding gather (fp32 + half) --------------------------
__global__ void embed_k(const int* __restrict__ tok, const float* __restrict__ ew,
                        float* __restrict__ x, __half* __restrict__ xh) {
    int s = blockIdx.x;
    int t = tok[s];
    for (int d = threadIdx.x; d < D; d += blockDim.x) {
        float v = ew[(size_t)t*D + d];
        x[(size_t)s*D + d] = v;
        xh[(size_t)s*D + d] = __float2half_rn(v);
    }
}

// ---------------- fp16 tensor-core GEMM (4-stage cp.async, NT only) -------
// C(MxN) fp32 = A_h(MxK) @ B_h(NxK)^T (+bias +res).
#define NSTG 4

template<int WGM, int WGN, int SMc, int SNc>
__global__ __launch_bounds__(WGM*WGN*32) void hgemm(
    const __half* __restrict__ A, const __half* __restrict__ B,
    const float* __restrict__ bias, const float* __restrict__ res,
    float* __restrict__ C, int M, int N, int K)
{
    constexpr int BM = WGM*SMc*16, BN = WGN*SNc*16, NT = WGM*WGN*32;
    constexpr int ASZ = BM*32, BSZ = BN*32;   // halfs per stage

    extern __shared__ __half sh[];
    __half* Asm = sh;
    __half* Bsm = sh + NSTG*ASZ;

    const int tid  = threadIdx.x;
    const int wid  = tid >> 5, lane = tid & 31;
    const int g    = lane >> 2, tg = lane & 3;
    const int r15  = lane & 15, khi = (lane >> 4) * 8;
    const int m0   = blockIdx.x * BM, n0 = blockIdx.y * BN;
    const int wm0  = (wid / WGN) * (SMc*16);
    const int wn0  = (wid % WGN) * (SNc*16);

    float acc[SMc][2*SNc][4] = {};

    auto load_stage = [&](int t) {
        const int k0 = t * 32;
        __half* As = Asm + (t & (NSTG-1))*ASZ;
        __half* Bs = Bsm + (t & (NSTG-1))*BSZ;
        #pragma unroll
        for (int cl = tid; cl < BM*4; cl += NT) {
            int m = cl >> 2, c = cl & 3;
            cp16(s2u(&As[m*32 + ((c ^ ((m>>1)&3)) << 3)]),
                 &A[(size_t)(m0 + m)*K + k0 + c*8]);
        }
        #pragma unroll
        for (int cl = tid; cl < BN*4; cl += NT) {
            int n = cl >> 2, c = cl & 3;
            cp16(s2u(&Bs[n*32 + ((c ^ ((n>>1)&3)) << 3)]),
                 &B[(size_t)(n0 + n)*K + k0 + c*8]);
        }
        cp_commit();
    };

    auto compute = [&](int t) {
        const __half* As = Asm + (t & (NSTG-1))*ASZ;
        const __half* Bs = Bsm + (t & (NSTG-1))*BSZ;
        #pragma unroll
        for (int kk = 0; kk < 2; kk++) {
            unsigned af[SMc][4], bf[SNc][4];
            #pragma unroll
            for (int i = 0; i < SMc; i++)
                ldm4(af[i], &As[swzh(wm0 + i*16 + r15, kk*16 + khi)]);
            #pragma unroll
            for (int j = 0; j < SNc; j++)
                ldm4(bf[j], &Bs[swzh(wn0 + j*16 + r15, kk*16 + khi)]);
            #pragma unroll
            for (int i = 0; i < SMc; i++)
                #pragma unroll
                for (int j = 0; j < SNc; j++) {
                    mma16816(acc[i][2*j  ], af[i], bf[j][0], bf[j][2]);
                    mma16816(acc[i][2*j+1], af[i], bf[j][1], bf[j][3]);
                }
        }
    };

    const int NIT = K / 32;    // 24 at every call site
    load_stage(0); load_stage(1); load_stage(2);
    for (int t = 0; t < NIT; t++) {
        if (t < NIT-2)       cp_wait<2>();
        else if (t == NIT-2) cp_wait<1>();
        else                 cp_wait<0>();
        __syncthreads();
        if (t + 3 < NIT) load_stage(t + 3);
        compute(t);
    }

    // ---- epilogue (fp32) ----
    #pragma unroll
    for (int i = 0; i < SMc; i++) {
        int mA = m0 + wm0 + i*16 + g;
        #pragma unroll
        for (int jj = 0; jj < 2*SNc; jj++) {
            int col = n0 + wn0 + (jj >> 1)*16 + (jj & 1)*8 + 2*tg;
            float b0 = bias ? bias[col] : 0.0f, b1 = bias ? bias[col+1] : 0.0f;
            float v0 = acc[i][jj][0] + b0, v1 = acc[i][jj][1] + b1;
            float v2 = acc[i][jj][2] + b0, v3 = acc[i][jj][3] + b1;
            if (res) {
                v0 += res[(size_t)mA*N + col];     v1 += res[(size_t)mA*N + col+1];
                v2 += res[(size_t)(mA+8)*N + col]; v3 += res[(size_t)(mA+8)*N + col+1];
            }
            *(float2*)&C[(size_t)mA*N + col]     = make_float2(v0, v1);
            *(float2*)&C[(size_t)(mA+8)*N + col] = make_float2(v2, v3);
        }
    }
}

// ---------------- fused ff1 + GLU GEMM (occupancy-tuned) -------------------
// z1 = A@B[0:768]^T + b[0:768], z2 = A@B[768:1536]^T + b[768:1536] on a
// 64x64 column tile; O = z1 * sigmoid(z2) in half.
// 128 threads, warps 2x2, warp tile 32x32 per panel, 48KB smem -> 4 CTAs/SM.
__global__ __launch_bounds__(128) void hgemm_glu(
    const __half* __restrict__ A, const __half* __restrict__ B,
    const float* __restrict__ bias, __half* __restrict__ O, int K)
{
    constexpr int BM = 64, BN = 64, NT = 128;
    constexpr int ASZ = BM*32, BSZ = 2*BN*32;   // halfs per stage (two B panels)

    extern __shared__ __half sh[];
    __half* Asm = sh;
    __half* Bsm = sh + NSTG*ASZ;

    const int tid  = threadIdx.x;
    const int wid  = tid >> 5, lane = tid & 31;
    const int g    = lane >> 2, tg = lane & 3;
    const int r15  = lane & 15, khi = (lane >> 4) * 8;
    const int m0   = blockIdx.x * BM, n0 = blockIdx.y * BN;
    const int wm0  = (wid >> 1) * 32;
    const int wn0  = (wid & 1) * 32;

    float accA[2][4][4] = {}, accB[2][4][4] = {};

    auto load_stage = [&](int t) {
        const int k0 = t * 32;
        __half* As = Asm + (t & (NSTG-1))*ASZ;
        __half* Bs = Bsm + (t & (NSTG-1))*BSZ;
        #pragma unroll
        for (int cl = tid; cl < BM*4; cl += NT) {
            int m = cl >> 2, c = cl & 3;
            cp16(s2u(&As[m*32 + ((c ^ ((m>>1)&3)) << 3)]),
                 &A[(size_t)(m0 + m)*K + k0 + c*8]);
        }
        #pragma unroll
        for (int cl = tid; cl < 2*BN*4; cl += NT) {
            int n = cl >> 2, c = cl & 3;               // n: 0..127 (two panels)
            int gr = (n < BN) ? (n0 + n) : (D + n0 + (n - BN));
            cp16(s2u(&Bs[n*32 + ((c ^ ((n>>1)&3)) << 3)]),
                 &B[(size_t)gr*K + k0 + c*8]);
        }
        cp_commit();
    };

    auto compute = [&](int t) {
        const __half* As = Asm + (t & (NSTG-1))*ASZ;
        const __half* Bs = Bsm + (t & (NSTG-1))*BSZ;
        #pragma unroll
        for (int kk = 0; kk < 2; kk++) {
            unsigned af[2][4], bf1[2][4], bf2[2][4];
            #pragma unroll
            for (int i = 0; i < 2; i++)
                ldm4(af[i], &As[swzh(wm0 + i*16 + r15, kk*16 + khi)]);
            #pragma unroll
            for (int j = 0; j < 2; j++) {
                ldm4(bf1[j], &Bs[swzh(wn0 + j*16 + r15,      kk*16 + khi)]);
                ldm4(bf2[j], &Bs[swzh(BN + wn0 + j*16 + r15, kk*16 + khi)]);
            }
            #pragma unroll
            for (int i = 0; i < 2; i++)
                #pragma unroll
                for (int j = 0; j < 2; j++) {
                    mma16816(accA[i][2*j  ], af[i], bf1[j][0], bf1[j][2]);
                    mma16816(accA[i][2*j+1], af[i], bf1[j][1], bf1[j][3]);
                    mma16816(accB[i][2*j  ], af[i], bf2[j][0], bf2[j][2]);
                    mma16816(accB[i][2*j+1], af[i], bf2[j][1], bf2[j][3]);
                }
        }
    };

    const int NIT = K / 32;
    load_stage(0); load_stage(1); load_stage(2);
    for (int t = 0; t < NIT; t++) {
        if (t < NIT-2)       cp_wait<2>();
        else if (t == NIT-2) cp_wait<1>();
        else                 cp_wait<0>();
        __syncthreads();
        if (t + 3 < NIT) load_stage(t + 3);
        compute(t);
    }

    // ---- epilogue: GLU, half out ----
    #pragma unroll
    for (int i = 0; i < 2; i++) {
        int mA = m0 + wm0 + i*16 + g;
        #pragma unroll
        for (int jj = 0; jj < 4; jj++) {
            int col = n0 + wn0 + (jj >> 1)*16 + (jj & 1)*8 + 2*tg;
            float b10 = bias[col], b11 = bias[col+1];
            float b20 = bias[D+col], b21 = bias[D+col+1];
            float z10 = accA[i][jj][0] + b10, z11 = accA[i][jj][1] + b11;
            float z12 = accA[i][jj][2] + b10, z13 = accA[i][jj][3] + b11;
            float z20 = accB[i][jj][0] + b20, z21 = accB[i][jj][1] + b21;
            float z22 = accB[i][jj][2] + b20, z23 = accB[i][jj][3] + b21;
            float o0 = z10 * (1.0f/(1.0f+expf(-z20)));
            float o1 = z11 * (1.0f/(1.0f+expf(-z21)));
            float o2 = z12 * (1.0f/(1.0f+expf(-z22)));
            float o3 = z13 * (1.0f/(1.0f+expf(-z23)));
            *(__half2*)&O[(size_t)mA*D + col]     = __floats2half2_rn(o0, o1);
            *(__half2*)&O[(size_t)(mA+8)*D + col] = __floats2half2_rn(o2, o3);
        }
    }
}

// ---------------- layernorm (fp32 in -> half out) --------------------------
__global__ __launch_bounds__(256) void ln_k(const float* __restrict__ x,
    const float* __restrict__ g, const float* __restrict__ b, __half* __restrict__ y)
{
    __shared__ float sh[8];
    int s = blockIdx.x;
    int tid = threadIdx.x;
    const float* row = x + (size_t)s * D;
    float v0 = row[tid], v1 = row[tid+256], v2 = row[tid+512];
    float sum = v0 + v1 + v2;
    #pragma unroll
    for (int o = 16; o > 0; o >>= 1) sum += __shfl_xor_sync(0xffffffffu, sum, o);
    if ((tid & 31) == 0) sh[tid >> 5] = sum;
    __syncthreads();
    float tot = sh[0]+sh[1]+sh[2]+sh[3]+sh[4]+sh[5]+sh[6]+sh[7];
    float mean = tot * (1.0f/768.0f);
    float d0 = v0 - mean, d1 = v1 - mean, d2 = v2 - mean;
    float vs = d0*d0 + d1*d1 + d2*d2;
    #pragma unroll
    for (int o = 16; o > 0; o >>= 1) vs += __shfl_xor_sync(0xffffffffu, vs, o);
    __syncthreads();
    if ((tid & 31) == 0) sh[tid >> 5] = vs;
    __syncthreads();
    float var = (sh[0]+sh[1]+sh[2]+sh[3]+sh[4]+sh[5]+sh[6]+sh[7]) * (1.0f/768.0f);
    float inv = rsqrtf(var + 1e-5f);
    y[(size_t)s*D + tid      ] = __float2half_rn(d0*inv*g[tid      ] + b[tid      ]);
    y[(size_t)s*D + tid + 256] = __float2half_rn(d1*inv*g[tid + 256] + b[tid + 256]);
    y[(size_t)s*D + tid + 512] = __float2half_rn(d2*inv*g[tid + 512] + b[tid + 512]);
}

// ---------------- position scan ------------------------------------------
__global__ void posscan_k(const float* __restrict__ h, float* __restrict__ x) {
    int d = blockIdx.x * 256 + threadIdx.x;
    if (d >= D) return;
    float acc = 0.0f;
    float c   = 0.0f;
    for (int s = 0; s < S; s++) {
        float hv = h[(size_t)s*(2*D) + d];
        float lg = h[(size_t)s*(2*D) + D + d];
        float lc = (hv >= 0.0f) ? (-log1pf(expf(-hv))) : (hv - log1pf(expf(hv)));
        acc += lc;
        float t = lg - acc;
        float mx = fmaxf(c, t), mn = fminf(c, t);
        c = mx + log1pf(expf(mn - mx));
        x[(size_t)s*D + d] += acc + c;
    }
}

// ---------------- attention pass A: per-chunk sums -------------------------
__global__ __launch_bounds__(1024) void attnA_k(const float* __restrict__ qkv,
    float* __restrict__ Asum, float* __restrict__ Zsum)
{
    int c = blockIdx.x, hh = blockIdx.y;
    int tid = threadIdx.x, lane = tid & 31, wid = tid >> 5;
    __shared__ float ek[CT][33], ev[CT][33];
    const float* base = qkv + (size_t)(c*CT + wid)*QKV_N + hh*96;
    ek[wid][lane] = expf(base[32 + lane]);
    ev[wid][lane] = expf(base[64 + lane]);
    __syncthreads();
    float m = 0.0f;
    #pragma unroll
    for (int t = 0; t < CT; t++) m = fmaf(ek[t][wid], ev[t][lane], m);
    Asum[(size_t)(((hh*NCH)+c)*DKV + wid)*DKV + lane] = m;
    if (wid == 0) {
        float z = 0.0f;
        #pragma unroll
        for (int t = 0; t < CT; t++) z += ek[t][lane];
        Zsum[(size_t)((hh*NCH)+c)*DKV + lane] = z;
    }
}

// ---------------- attention pass C: carry-from-Asum + intra-chunk ----------
__global__ __launch_bounds__(1024) void attnC_k(const float* __restrict__ qkv,
    const float* __restrict__ Asum, const float* __restrict__ Zsum,
    __half* __restrict__ att)
{
    int c = blockIdx.x, hh = blockIdx.y;
    int tid = threadIdx.x, lane = tid & 31, wid = tid >> 5;
    __shared__ float eq[CT][33], ek[CT][33], ev[CT][33], P[CT][33], M0[DKV][33];
    __shared__ float z0[DKV];
    const float* base = qkv + (size_t)(c*CT + wid)*QKV_N + hh*96;
    eq[wid][lane] = expf(base[      lane]);
    ek[wid][lane] = expf(base[32 +  lane]);
    ev[wid][lane] = expf(base[64 +  lane]);
    {
        float m0 = 0.0f;
        for (int cc = 0; cc < c; cc++)
            m0 += Asum[(size_t)(((hh*NCH)+cc)*DKV + wid)*DKV + lane];
        M0[wid][lane] = m0;
    }
    if (tid < DKV) {
        float z = 0.0f;
        for (int cc = 0; cc < c; cc++)
            z += Zsum[(size_t)((hh*NCH)+cc)*DKV + tid];
        z0[tid] = z;
    }
    __syncthreads();
    float p = 0.0f;
    #pragma unroll
    for (int k = 0; k < DKV; k++) p = fmaf(eq[wid][k], ek[lane][k], p);
    P[wid][lane] = p;
    __syncthreads();
    float num = 0.0f, den = 0.0f;
    #pragma unroll
    for (int k = 0; k < DKV; k++) {
        float q = eq[wid][k];
        num = fmaf(q, M0[k][lane], num);
        den = fmaf(q, z0[k], den);
    }
    for (int s2 = 0; s2 <= wid; s2++) {
        float ps = P[wid][s2];
        num = fmaf(ps, ev[s2][lane], num);
        den += ps;
    }
    att[(size_t)(c*CT + wid)*D + hh*DKV + lane] = __float2half_rn(logf(num) - logf(den));
}

// ---------------- launcher -----------------------------------------------
extern "C" void kernel_launch(void* const* d_in, const int* in_sizes, int n_in,
                              void* d_out, int out_size)
{
    const int*   tok  = (const int*)  d_in[0];
    const float* embw = (const float*)d_in[1];
    const float* posw = (const float*)d_in[2];
    const float* posb = (const float*)d_in[3];
    const float* ln1g = (const float*)d_in[4];
    const float* ln1b = (const float*)d_in[5];
    const float* qkvw = (const float*)d_in[6];
    const float* qkvb = (const float*)d_in[7];
    const float* ffw1 = (const float*)d_in[8];
    const float* ffb1 = (const float*)d_in[9];
    const float* ffw2 = (const float*)d_in[10];
    const float* lnfg = (const float*)d_in[11];
    const float* lnfb = (const float*)d_in[12];
    float* out = (float*)d_out;

    float *x,*hh,*qkv,*Asum,*Zsum;
    __half *xh,*xnh,*atth,*gluh,*poswh,*qkvwh,*ff1wh,*ff2wh,*embwh;
    cudaGetSymbolAddress((void**)&x,    g_x);
    cudaGetSymbolAddress((void**)&hh,   g_h);
    cudaGetSymbolAddress((void**)&qkv,  g_qkv);
    cudaGetSymbolAddress((void**)&Asum, g_Asum);
    cudaGetSymbolAddress((void**)&Zsum, g_Zsum);
    cudaGetSymbolAddress((void**)&xh,    g_xh);
    cudaGetSymbolAddress((void**)&xnh,   g_xnh);
    cudaGetSymbolAddress((void**)&atth,  g_atth);
    cudaGetSymbolAddress((void**)&gluh,  g_gluh);
    cudaGetSymbolAddress((void**)&poswh, g_poswh);
    cudaGetSymbolAddress((void**)&qkvwh, g_qkvwh);
    cudaGetSymbolAddress((void**)&ff1wh, g_ff1wh);
    cudaGetSymbolAddress((void**)&ff2wh, g_ff2wh);
    cudaGetSymbolAddress((void**)&embwh, g_embwh);

    // smem per config: NSTG*(BM+BN)*32 halfs
    const int sm_A = NSTG*( 64+128)*32*2;   // 49152  (64x128, pos/qkv/logits)
    const int sm_B = NSTG*( 64+ 64)*32*2;   // 32768  (64x64,  ff2)
    const int sm_G = NSTG*( 64+128)*32*2;   // 49152  (ff1+glu dual 64-panel)
    cudaFuncSetAttribute(hgemm<2,4,2,2>, cudaFuncAttributeMaxDynamicSharedMemorySize, sm_A);
    cudaFuncSetAttribute(hgemm<2,2,2,2>, cudaFuncAttributeMaxDynamicSharedMemorySize, sm_B);
    cudaFuncSetAttribute(hgemm_glu,      cudaFuncAttributeMaxDynamicSharedMemorySize, sm_G);

    // ---- weight prep (every call; deterministic) ----
    tconv_k<<<dim3(2*D/32,  D/32, 1     ), dim3(32,8)>>>(posw, poswh, D, 2*D);
    tconv_k<<<dim3(QKV_N/32,D/32, LAYERS), dim3(32,8)>>>(qkvw, qkvwh, D, QKV_N);
    tconv_k<<<dim3(FF_N/32, D/32, LAYERS), dim3(32,8)>>>(ffw1, ff1wh, D, FF_N);
    tconv_k<<<dim3(D/32,    D/32, LAYERS), dim3(32,8)>>>(ffw2, ff2wh, D, D);
    conv_k<<<1024, 256>>>(embw, embwh, (size_t)VSZ*D/2);

    // ---- embed + position recurrence ----
    embed_k<<<S, 256>>>(tok, embw, x, xh);
    hgemm<2,4,2,2><<<dim3(S/64, 2*D/128), 256, sm_A>>>(
        xh, poswh, posb, nullptr, hh, S, 2*D, D);
    posscan_k<<<3, 256>>>(hh, x);

    for (int l = 0; l < LAYERS; l++) {
        ln_k<<<S, 256>>>(x, ln1g + (size_t)l*D, ln1b + (size_t)l*D, xnh);
        hgemm<2,4,2,2><<<dim3(S/64, QKV_N/128), 256, sm_A>>>(
            xnh, qkvwh + (size_t)l*D*QKV_N, qkvb + (size_t)l*QKV_N, nullptr, qkv, S, QKV_N, D);
        attnA_k<<<dim3(NCH, HEADS), 1024>>>(qkv, Asum, Zsum);
        attnC_k<<<dim3(NCH, HEADS), 1024>>>(qkv, Asum, Zsum, atth);
        hgemm_glu<<<dim3(S/64, D/64), 128, sm_G>>>(
            atth, ff1wh + (size_t)l*D*FF_N, ffb1 + (size_t)l*FF_N, gluh, D);
        hgemm<2,2,2,2><<<dim3(S/64, D/64), 128, sm_B>>>(
            gluh, ff2wh + (size_t)l*D*D, nullptr, x, x, S, D, D);
    }

    ln_k<<<S, 256>>>(x, lnfg, lnfb, xnh);
    hgemm<2,4,2,2><<<dim3(S/64, VSZ/128), 256, sm_A>>>(
        xnh, embwh, nullptr, nullptr, out, S, VSZ, D);
}

// round 13
// speedup vs baseline: 1.0379x; 1.0379x over previous
#include <cuda_runtime.h>
#include <cuda_fp16.h>
#include <math.h>

#define S 1024
#define D 768
#define LAYERS 12
#define HEADS 24
#define DKV 32
#define QKV_N 2304
#define FF_N 1536
#define VSZ 50304
#define NCH 32
#define CT 32

// ---------------- scratch -----------------------------------------------
__device__ float g_x[S*D];
__device__ float g_h[S*2*D];
__device__ float g_qkv[S*QKV_N];
__device__ float g_Asum[HEADS*NCH*DKV*DKV];
__device__ float g_Zsum[HEADS*NCH*DKV];

__device__ __half g_xh[S*D];
__device__ __half g_xnh[S*D];
__device__ __half g_atth[S*D];
__device__ __half g_gluh[S*D];
__device__ __half g_poswh[D*2*D];
__device__ __half g_qkvwh[LAYERS*D*QKV_N];
__device__ __half g_ff1wh[LAYERS*D*FF_N];
__device__ __half g_ff2wh[LAYERS*D*D];
__device__ __half g_embwh[(size_t)VSZ*D];

// ---------------- low-level helpers --------------------------------------
__device__ __forceinline__ unsigned s2u(const void* p) {
    return (unsigned)__cvta_generic_to_shared(p);
}
__device__ __forceinline__ void cp16(unsigned dst, const void* src) {
    asm volatile("cp.async.cg.shared.global [%0], [%1], 16;\n" :: "r"(dst), "l"(src));
}
__device__ __forceinline__ void cp_commit() {
    asm volatile("cp.async.commit_group;\n");
}
template<int N>
__device__ __forceinline__ void cp_wait() {
    asm volatile("cp.async.wait_group %0;\n" :: "n"(N));
}
__device__ __forceinline__ void ldm4(unsigned* r, const __half* p) {
    unsigned a = s2u(p);
    asm volatile("ldmatrix.sync.aligned.m8n8.x4.shared.b16 {%0,%1,%2,%3}, [%4];"
        : "=r"(r[0]), "=r"(r[1]), "=r"(r[2]), "=r"(r[3]) : "r"(a));
}
__device__ __forceinline__ void mma16816(float* c, const unsigned* a, unsigned b0, unsigned b1) {
    asm volatile(
        "mma.sync.aligned.m16n8k16.row.col.f32.f16.f16.f32 "
        "{%0,%1,%2,%3},{%4,%5,%6,%7},{%8,%9},{%0,%1,%2,%3};"
        : "+f"(c[0]), "+f"(c[1]), "+f"(c[2]), "+f"(c[3])
        : "r"(a[0]), "r"(a[1]), "r"(a[2]), "r"(a[3]), "r"(b0), "r"(b1));
}
// swizzled index (half units) in a [rows][32] k-major half tile
__device__ __forceinline__ int swzh(int r, int k) {
    return r*32 + ((((k >> 3) ^ ((r >> 1) & 3)) << 3) | (k & 7));
}

// ---------------- weight prep: transpose + convert (wide stores) ----------
// src: [z][R][Cc] fp32 -> dst: [z][Cc][R] half.  Tile: 64 R-rows x 32 Cc-cols.
__global__ __launch_bounds__(256) void tconv_k(const float* __restrict__ src,
                                               __half* __restrict__ dst, int R, int Cc)
{
    __shared__ float t[64][33];
    int c0 = blockIdx.x*32, r0 = blockIdx.y*64, z = blockIdx.z;
    src += (size_t)z*R*Cc;
    dst += (size_t)z*R*Cc;
    int tx = threadIdx.x, ty = threadIdx.y;   // 32 x 8
    #pragma unroll
    for (int i = 0; i < 8; i++)
        t[ty + 8*i][tx] = src[(size_t)(r0 + ty + 8*i)*Cc + c0 + tx];
    __syncthreads();
    int tid = ty*32 + tx;
    int cc = tid >> 3, w = tid & 7;           // output row cc (0..31), slot group w
    __half* orow = dst + (size_t)(c0 + cc)*R + r0;
    #pragma unroll
    for (int sb = 0; sb < 2; sb++) {
        int s = w + sb*8;                     // 16 slots of 4 halves across 64 R vals
        __half2 h[2];
        h[0] = __floats2half2_rn(t[4*s  ][cc], t[4*s+1][cc]);
        h[1] = __floats2half2_rn(t[4*s+2][cc], t[4*s+3][cc]);
        *(uint2*)&orow[4*s] = *(uint2*)h;
    }
}
// straight convert fp32 -> half (float4 in, 8B out)
__global__ __launch_bounds__(256) void conv_k(const float* __restrict__ src,
                                              __half* __restrict__ dst, size_t n4)
{
    size_t stride = (size_t)gridDim.x * blockDim.x;
    for (size_t i = (size_t)blockIdx.x*blockDim.x + threadIdx.x; i < n4; i += stride) {
        float4 v = ((const float4*)src)[i];
        __half2 h[2];
        h[0] = __floats2half2_rn(v.x, v.y);
        h[1] = __floats2half2_rn(v.z, v.w);
        ((uint2*)dst)[i] = *(uint2*)h;
    }
}

// ---------------- embedding gather (fp32 + half) --------------------------
__global__ void embed_k(const int* __restrict__ tok, const float* __restrict__ ew,
                        float* __restrict__ x, __half* __restrict__ xh) {
    int s = blockIdx.x;
    int t = tok[s];
    for (int d = threadIdx.x; d < D; d += blockDim.x) {
        float v = ew[(size_t)t*D + d];
        x[(size_t)s*D + d] = v;
        xh[(size_t)s*D + d] = __float2half_rn(v);
    }
}

// ---------------- fp16 tensor-core GEMM (4-stage cp.async, NT only) -------
// C(MxN) fp32 = A_h(MxK) @ B_h(NxK)^T (+bias +res).
#define NSTG 4

template<int WGM, int WGN, int SMc, int SNc>
__global__ __launch_bounds__(WGM*WGN*32) void hgemm(
    const __half* __restrict__ A, const __half* __restrict__ B,
    const float* __restrict__ bias, const float* __restrict__ res,
    float* __restrict__ C, int M, int N, int K)
{
    constexpr int BM = WGM*SMc*16, BN = WGN*SNc*16, NT = WGM*WGN*32;
    constexpr int ASZ = BM*32, BSZ = BN*32;   // halfs per stage

    extern __shared__ __half sh[];
    __half* Asm = sh;
    __half* Bsm = sh + NSTG*ASZ;

    const int tid  = threadIdx.x;
    const int wid  = tid >> 5, lane = tid & 31;
    const int g    = lane >> 2, tg = lane & 3;
    const int r15  = lane & 15, khi = (lane >> 4) * 8;
    const int m0   = blockIdx.x * BM, n0 = blockIdx.y * BN;
    const int wm0  = (wid / WGN) * (SMc*16);
    const int wn0  = (wid % WGN) * (SNc*16);

    float acc[SMc][2*SNc][4] = {};

    auto load_stage = [&](int t) {
        const int k0 = t * 32;
        __half* As = Asm + (t & (NSTG-1))*ASZ;
        __half* Bs = Bsm + (t & (NSTG-1))*BSZ;
        #pragma unroll
        for (int cl = tid; cl < BM*4; cl += NT) {
            int m = cl >> 2, c = cl & 3;
            cp16(s2u(&As[m*32 + ((c ^ ((m>>1)&3)) << 3)]),
                 &A[(size_t)(m0 + m)*K + k0 + c*8]);
        }
        #pragma unroll
        for (int cl = tid; cl < BN*4; cl += NT) {
            int n = cl >> 2, c = cl & 3;
            cp16(s2u(&Bs[n*32 + ((c ^ ((n>>1)&3)) << 3)]),
                 &B[(size_t)(n0 + n)*K + k0 + c*8]);
        }
        cp_commit();
    };

    auto compute = [&](int t) {
        const __half* As = Asm + (t & (NSTG-1))*ASZ;
        const __half* Bs = Bsm + (t & (NSTG-1))*BSZ;
        #pragma unroll
        for (int kk = 0; kk < 2; kk++) {
            unsigned af[SMc][4], bf[SNc][4];
            #pragma unroll
            for (int i = 0; i < SMc; i++)
                ldm4(af[i], &As[swzh(wm0 + i*16 + r15, kk*16 + khi)]);
            #pragma unroll
            for (int j = 0; j < SNc; j++)
                ldm4(bf[j], &Bs[swzh(wn0 + j*16 + r15, kk*16 + khi)]);
            #pragma unroll
            for (int i = 0; i < SMc; i++)
                #pragma unroll
                for (int j = 0; j < SNc; j++) {
                    mma16816(acc[i][2*j  ], af[i], bf[j][0], bf[j][2]);
                    mma16816(acc[i][2*j+1], af[i], bf[j][1], bf[j][3]);
                }
        }
    };

    const int NIT = K / 32;    // 24 at every call site
    load_stage(0); load_stage(1); load_stage(2);
    for (int t = 0; t < NIT; t++) {
        if (t < NIT-2)       cp_wait<2>();
        else if (t == NIT-2) cp_wait<1>();
        else                 cp_wait<0>();
        __syncthreads();
        if (t + 3 < NIT) load_stage(t + 3);
        compute(t);
        __syncthreads();
    }

    // ---- epilogue (fp32) ----
    #pragma unroll
    for (int i = 0; i < SMc; i++) {
        int mA = m0 + wm0 + i*16 + g;
        #pragma unroll
        for (int jj = 0; jj < 2*SNc; jj++) {
            int col = n0 + wn0 + (jj >> 1)*16 + (jj & 1)*8 + 2*tg;
            float b0 = bias ? bias[col] : 0.0f, b1 = bias ? bias[col+1] : 0.0f;
            float v0 = acc[i][jj][0] + b0, v1 = acc[i][jj][1] + b1;
            float v2 = acc[i][jj][2] + b0, v3 = acc[i][jj][3] + b1;
            if (res) {
                v0 += res[(size_t)mA*N + col];     v1 += res[(size_t)mA*N + col+1];
                v2 += res[(size_t)(mA+8)*N + col]; v3 += res[(size_t)(mA+8)*N + col+1];
            }
            *(float2*)&C[(size_t)mA*N + col]     = make_float2(v0, v1);
            *(float2*)&C[(size_t)(mA+8)*N + col] = make_float2(v2, v3);
        }
    }
}

// ---------------- fused ff1 + GLU GEMM (occupancy-tuned) -------------------
// z1 = A@B[0:768]^T + b[0:768], z2 = A@B[768:1536]^T + b[768:1536] on a
// 64x64 column tile; O = z1 * sigmoid(z2) in half.
// 128 threads, warps 2x2, warp tile 32x32 per panel, 48KB smem -> 4 CTAs/SM.
__global__ __launch_bounds__(128) void hgemm_glu(
    const __half* __restrict__ A, const __half* __restrict__ B,
    const float* __restrict__ bias, __half* __restrict__ O, int K)
{
    constexpr int BM = 64, BN = 64, NT = 128;
    constexpr int ASZ = BM*32, BSZ = 2*BN*32;   // halfs per stage (two B panels)

    extern __shared__ __half sh[];
    __half* Asm = sh;
    __half* Bsm = sh + NSTG*ASZ;

    const int tid  = threadIdx.x;
    const int wid  = tid >> 5, lane = tid & 31;
    const int g    = lane >> 2, tg = lane & 3;
    const int r15  = lane & 15, khi = (lane >> 4) * 8;
    const int m0   = blockIdx.x * BM, n0 = blockIdx.y * BN;
    const int wm0  = (wid >> 1) * 32;
    const int wn0  = (wid & 1) * 32;

    float accA[2][4][4] = {}, accB[2][4][4] = {};

    auto load_stage = [&](int t) {
        const int k0 = t * 32;
        __half* As = Asm + (t & (NSTG-1))*ASZ;
        __half* Bs = Bsm + (t & (NSTG-1))*BSZ;
        #pragma unroll
        for (int cl = tid; cl < BM*4; cl += NT) {
            int m = cl >> 2, c = cl & 3;
            cp16(s2u(&As[m*32 + ((c ^ ((m>>1)&3)) << 3)]),
                 &A[(size_t)(m0 + m)*K + k0 + c*8]);
        }
        #pragma unroll
        for (int cl = tid; cl < 2*BN*4; cl += NT) {
            int n = cl >> 2, c = cl & 3;               // n: 0..127 (two panels)
            int gr = (n < BN) ? (n0 + n) : (D + n0 + (n - BN));
            cp16(s2u(&Bs[n*32 + ((c ^ ((n>>1)&3)) << 3)]),
                 &B[(size_t)gr*K + k0 + c*8]);
        }
        cp_commit();
    };

    auto compute = [&](int t) {
        const __half* As = Asm + (t & (NSTG-1))*ASZ;
        const __half* Bs = Bsm + (t & (NSTG-1))*BSZ;
        #pragma unroll
        for (int kk = 0; kk < 2; kk++) {
            unsigned af[2][4], bf1[2][4], bf2[2][4];
            #pragma unroll
            for (int i = 0; i < 2; i++)
                ldm4(af[i], &As[swzh(wm0 + i*16 + r15, kk*16 + khi)]);
            #pragma unroll
            for (int j = 0; j < 2; j++) {
                ldm4(bf1[j], &Bs[swzh(wn0 + j*16 + r15,      kk*16 + khi)]);
                ldm4(bf2[j], &Bs[swzh(BN + wn0 + j*16 + r15, kk*16 + khi)]);
            }
            #pragma unroll
            for (int i = 0; i < 2; i++)
                #pragma unroll
                for (int j = 0; j < 2; j++) {
                    mma16816(accA[i][2*j  ], af[i], bf1[j][0], bf1[j][2]);
                    mma16816(accA[i][2*j+1], af[i], bf1[j][1], bf1[j][3]);
                    mma16816(accB[i][2*j  ], af[i], bf2[j][0], bf2[j][2]);
                    mma16816(accB[i][2*j+1], af[i], bf2[j][1], bf2[j][3]);
                }
        }
    };

    const int NIT = K / 32;
    load_stage(0); load_stage(1); load_stage(2);
    for (int t = 0; t < NIT; t++) {
        if (t < NIT-2)       cp_wait<2>();
        else if (t == NIT-2) cp_wait<1>();
        else                 cp_wait<0>();
        __syncthreads();
        if (t + 3 < NIT) load_stage(t + 3);
        compute(t);
        __syncthreads();
    }

    // ---- epilogue: GLU, half out ----
    #pragma unroll
    for (int i = 0; i < 2; i++) {
        int mA = m0 + wm0 + i*16 + g;
        #pragma unroll
        for (int jj = 0; jj < 4; jj++) {
            int col = n0 + wn0 + (jj >> 1)*16 + (jj & 1)*8 + 2*tg;
            float b10 = bias[col], b11 = bias[col+1];
            float b20 = bias[D+col], b21 = bias[D+col+1];
            float z10 = accA[i][jj][0] + b10, z11 = accA[i][jj][1] + b11;
            float z12 = accA[i][jj][2] + b10, z13 = accA[i][jj][3] + b11;
            float z20 = accB[i][jj][0] + b20, z21 = accB[i][jj][1] + b21;
            float z22 = accB[i][jj][2] + b20, z23 = accB[i][jj][3] + b21;
            float o0 = z10 * (1.0f/(1.0f+expf(-z20)));
            float o1 = z11 * (1.0f/(1.0f+expf(-z21)));
            float o2 = z12 * (1.0f/(1.0f+expf(-z22)));
            float o3 = z13 * (1.0f/(1.0f+expf(-z23)));
            *(__half2*)&O[(size_t)mA*D + col]     = __floats2half2_rn(o0, o1);
            *(__half2*)&O[(size_t)(mA+8)*D + col] = __floats2half2_rn(o2, o3);
        }
    }
}

// ---------------- layernorm (fp32 in -> half out) --------------------------
__global__ __launch_bounds__(256) void ln_k(const float* __restrict__ x,
    const float* __restrict__ g, const float* __restrict__ b, __half* __restrict__ y)
{
    __shared__ float sh[8];
    int s = blockIdx.x;
    int tid = threadIdx.x;
    const float* row = x + (size_t)s * D;
    float v0 = row[tid], v1 = row[tid+256], v2 = row[tid+512];
    float sum = v0 + v1 + v2;
    #pragma unroll
    for (int o = 16; o > 0; o >>= 1) sum += __shfl_xor_sync(0xffffffffu, sum, o);
    if ((tid & 31) == 0) sh[tid >> 5] = sum;
    __syncthreads();
    float tot = sh[0]+sh[1]+sh[2]+sh[3]+sh[4]+sh[5]+sh[6]+sh[7];
    float mean = tot * (1.0f/768.0f);
    float d0 = v0 - mean, d1 = v1 - mean, d2 = v2 - mean;
    float vs = d0*d0 + d1*d1 + d2*d2;
    #pragma unroll
    for (int o = 16; o > 0; o >>= 1) vs += __shfl_xor_sync(0xffffffffu, vs, o);
    __syncthreads();
    if ((tid & 31) == 0) sh[tid >> 5] = vs;
    __syncthreads();
    float var = (sh[0]+sh[1]+sh[2]+sh[3]+sh[4]+sh[5]+sh[6]+sh[7]) * (1.0f/768.0f);
    float inv = rsqrtf(var + 1e-5f);
    y[(size_t)s*D + tid      ] = __float2half_rn(d0*inv*g[tid      ] + b[tid      ]);
    y[(size_t)s*D + tid + 256] = __float2half_rn(d1*inv*g[tid + 256] + b[tid + 256]);
    y[(size_t)s*D + tid + 512] = __float2half_rn(d2*inv*g[tid + 512] + b[tid + 512]);
}

// ---------------- position scan ------------------------------------------
__global__ void posscan_k(const float* __restrict__ h, float* __restrict__ x) {
    int d = blockIdx.x * 256 + threadIdx.x;
    if (d >= D) return;
    float acc = 0.0f;
    float c   = 0.0f;
    for (int s = 0; s < S; s++) {
        float hv = h[(size_t)s*(2*D) + d];
        float lg = h[(size_t)s*(2*D) + D + d];
        float lc = (hv >= 0.0f) ? (-log1pf(expf(-hv))) : (hv - log1pf(expf(hv)));
        acc += lc;
        float t = lg - acc;
        float mx = fmaxf(c, t), mn = fminf(c, t);
        c = mx + log1pf(expf(mn - mx));
        x[(size_t)s*D + d] += acc + c;
    }
}

// ---------------- attention pass A: per-chunk sums -------------------------
__global__ __launch_bounds__(1024) void attnA_k(const float* __restrict__ qkv,
    float* __restrict__ Asum, float* __restrict__ Zsum)
{
    int c = blockIdx.x, hh = blockIdx.y;
    int tid = threadIdx.x, lane = tid & 31, wid = tid >> 5;
    __shared__ float ek[CT][33], ev[CT][33];
    const float* base = qkv + (size_t)(c*CT + wid)*QKV_N + hh*96;
    ek[wid][lane] = expf(base[32 + lane]);
    ev[wid][lane] = expf(base[64 + lane]);
    __syncthreads();
    float m = 0.0f;
    #pragma unroll
    for (int t = 0; t < CT; t++) m = fmaf(ek[t][wid], ev[t][lane], m);
    Asum[(size_t)(((hh*NCH)+c)*DKV + wid)*DKV + lane] = m;
    if (wid == 0) {
        float z = 0.0f;
        #pragma unroll
        for (int t = 0; t < CT; t++) z += ek[t][lane];
        Zsum[(size_t)((hh*NCH)+c)*DKV + lane] = z;
    }
}

// ---------------- attention pass C: carry-from-Asum + intra-chunk ----------
__global__ __launch_bounds__(1024) void attnC_k(const float* __restrict__ qkv,
    const float* __restrict__ Asum, const float* __restrict__ Zsum,
    __half* __restrict__ att)
{
    int c = blockIdx.x, hh = blockIdx.y;
    int tid = threadIdx.x, lane = tid & 31, wid = tid >> 5;
    __shared__ float eq[CT][33], ek[CT][33], ev[CT][33], P[CT][33], M0[DKV][33];
    __shared__ float z0[DKV];
    const float* base = qkv + (size_t)(c*CT + wid)*QKV_N + hh*96;
    eq[wid][lane] = expf(base[      lane]);
    ek[wid][lane] = expf(base[32 +  lane]);
    ev[wid][lane] = expf(base[64 +  lane]);
    {
        float m0 = 0.0f;
        for (int cc = 0; cc < c; cc++)
            m0 += Asum[(size_t)(((hh*NCH)+cc)*DKV + wid)*DKV + lane];
        M0[wid][lane] = m0;
    }
    if (tid < DKV) {
        float z = 0.0f;
        for (int cc = 0; cc < c; cc++)
            z += Zsum[(size_t)((hh*NCH)+cc)*DKV + tid];
        z0[tid] = z;
    }
    __syncthreads();
    float p = 0.0f;
    #pragma unroll
    for (int k = 0; k < DKV; k++) p = fmaf(eq[wid][k], ek[lane][k], p);
    P[wid][lane] = p;
    __syncthreads();
    float num = 0.0f, den = 0.0f;
    #pragma unroll
    for (int k = 0; k < DKV; k++) {
        float q = eq[wid][k];
        num = fmaf(q, M0[k][lane], num);
        den = fmaf(q, z0[k], den);
    }
    for (int s2 = 0; s2 <= wid; s2++) {
        float ps = P[wid][s2];
        num = fmaf(ps, ev[s2][lane], num);
        den += ps;
    }
    att[(size_t)(c*CT + wid)*D + hh*DKV + lane] = __float2half_rn(logf(num) - logf(den));
}

// ---------------- launcher -----------------------------------------------
extern "C" void kernel_launch(void* const* d_in, const int* in_sizes, int n_in,
                              void* d_out, int out_size)
{
    const int*   tok  = (const int*)  d_in[0];
    const float* embw = (const float*)d_in[1];
    const float* posw = (const float*)d_in[2];
    const float* posb = (const float*)d_in[3];
    const float* ln1g = (const float*)d_in[4];
    const float* ln1b = (const float*)d_in[5];
    const float* qkvw = (const float*)d_in[6];
    const float* qkvb = (const float*)d_in[7];
    const float* ffw1 = (const float*)d_in[8];
    const float* ffb1 = (const float*)d_in[9];
    const float* ffw2 = (const float*)d_in[10];
    const float* lnfg = (const float*)d_in[11];
    const float* lnfb = (const float*)d_in[12];
    float* out = (float*)d_out;

    float *x,*hh,*qkv,*Asum,*Zsum;
    __half *xh,*xnh,*atth,*gluh,*poswh,*qkvwh,*ff1wh,*ff2wh,*embwh;
    cudaGetSymbolAddress((void**)&x,    g_x);
    cudaGetSymbolAddress((void**)&hh,   g_h);
    cudaGetSymbolAddress((void**)&qkv,  g_qkv);
    cudaGetSymbolAddress((void**)&Asum, g_Asum);
    cudaGetSymbolAddress((void**)&Zsum, g_Zsum);
    cudaGetSymbolAddress((void**)&xh,    g_xh);
    cudaGetSymbolAddress((void**)&xnh,   g_xnh);
    cudaGetSymbolAddress((void**)&atth,  g_atth);
    cudaGetSymbolAddress((void**)&gluh,  g_gluh);
    cudaGetSymbolAddress((void**)&poswh, g_poswh);
    cudaGetSymbolAddress((void**)&qkvwh, g_qkvwh);
    cudaGetSymbolAddress((void**)&ff1wh, g_ff1wh);
    cudaGetSymbolAddress((void**)&ff2wh, g_ff2wh);
    cudaGetSymbolAddress((void**)&embwh, g_embwh);

    // smem per config: NSTG*(BM+BN)*32 halfs
    const int sm_A = NSTG*( 64+128)*32*2;   // 49152  (64x128, pos/qkv)
    const int sm_B = NSTG*( 64+ 64)*32*2;   // 32768  (64x64,  ff2)
    const int sm_C = NSTG*(128+128)*32*2;   // 65536  (128x128, logits)
    const int sm_G = NSTG*( 64+128)*32*2;   // 49152  (ff1+glu dual 64-panel)
    cudaFuncSetAttribute(hgemm<2,4,2,2>, cudaFuncAttributeMaxDynamicSharedMemorySize, sm_A);
    cudaFuncSetAttribute(hgemm<2,2,2,2>, cudaFuncAttributeMaxDynamicSharedMemorySize, sm_B);
    cudaFuncSetAttribute(hgemm<2,4,4,2>, cudaFuncAttributeMaxDynamicSharedMemorySize, sm_C);
    cudaFuncSetAttribute(hgemm_glu,      cudaFuncAttributeMaxDynamicSharedMemorySize, sm_G);

    // ---- weight prep (every call; deterministic) ----
    tconv_k<<<dim3(2*D/32,  D/64, 1     ), dim3(32,8)>>>(posw, poswh, D, 2*D);
    tconv_k<<<dim3(QKV_N/32,D/64, LAYERS), dim3(32,8)>>>(qkvw, qkvwh, D, QKV_N);
    tconv_k<<<dim3(FF_N/32, D/64, LAYERS), dim3(32,8)>>>(ffw1, ff1wh, D, FF_N);
    tconv_k<<<dim3(D/32,    D/64, LAYERS), dim3(32,8)>>>(ffw2, ff2wh, D, D);
    conv_k<<<1024, 256>>>(embw, embwh, (size_t)VSZ*D/4);

    // ---- embed + position recurrence ----
    embed_k<<<S, 256>>>(tok, embw, x, xh);
    hgemm<2,4,2,2><<<dim3(S/64, 2*D/128), 256, sm_A>>>(
        xh, poswh, posb, nullptr, hh, S, 2*D, D);
    posscan_k<<<3, 256>>>(hh, x);

    for (int l = 0; l < LAYERS; l++) {
        ln_k<<<S, 256>>>(x, ln1g + (size_t)l*D, ln1b + (size_t)l*D, xnh);
        hgemm<2,4,2,2><<<dim3(S/64, QKV_N/128), 256, sm_A>>>(
            xnh, qkvwh + (size_t)l*D*QKV_N, qkvb + (size_t)l*QKV_N, nullptr, qkv, S, QKV_N, D);
        attnA_k<<<dim3(NCH, HEADS), 1024>>>(qkv, Asum, Zsum);
        attnC_k<<<dim3(NCH, HEADS), 1024>>>(qkv, Asum, Zsum, atth);
        hgemm_glu<<<dim3(S/64, D/64), 128, sm_G>>>(
            atth, ff1wh + (size_t)l*D*FF_N, ffb1 + (size_t)l*FF_N, gluh, D);
        hgemm<2,2,2,2><<<dim3(S/64, D/64), 128, sm_B>>>(
            gluh, ff2wh + (size_t)l*D*D, nullptr, x, x, S, D, D);
    }

    ln_k<<<S, 256>>>(x, lnfg, lnfb, xnh);
    hgemm<2,4,4,2><<<dim3(S/128, VSZ/128), 256, sm_C>>>(
        xnh, embwh, nullptr, nullptr, out, S, VSZ, D);
}

// round 14
// speedup vs baseline: 1.4442x; 1.3915x over previous
#include <cuda_runtime.h>
#include <cuda_fp16.h>
#include <math.h>

#define S 1024
#define D 768
#define LAYERS 12
#define HEADS 24
#define DKV 32
#define QKV_N 2304
#define FF_N 1536
#define VSZ 50304
#define NCH 32
#define CT 32

// ---------------- scratch -----------------------------------------------
__device__ float g_x[S*D];
__device__ float g_h[S*2*D];
__device__ float g_qkv[S*QKV_N];
__device__ float g_Asum[HEADS*NCH*DKV*DKV];
__device__ float g_Zsum[HEADS*NCH*DKV];
__device__ float g_ps_sum[NCH*D];
__device__ float g_ps_lse[NCH*D];
__device__ float g_ps_accb[NCH*D];
__device__ float g_ps_R[NCH*D];

__device__ __half g_xh[S*D];
__device__ __half g_xnh[S*D];
__device__ __half g_atth[S*D];
__device__ __half g_gluh[S*D];
__device__ __half g_poswh[D*2*D];
__device__ __half g_qkvwh[LAYERS*D*QKV_N];
__device__ __half g_ff1wh[LAYERS*D*FF_N];
__device__ __half g_ff2wh[LAYERS*D*D];
__device__ __half g_embwh[(size_t)VSZ*D];

// ---------------- low-level helpers --------------------------------------
__device__ __forceinline__ unsigned s2u(const void* p) {
    return (unsigned)__cvta_generic_to_shared(p);
}
__device__ __forceinline__ void cp16(unsigned dst, const void* src) {
    asm volatile("cp.async.cg.shared.global [%0], [%1], 16;\n" :: "r"(dst), "l"(src));
}
__device__ __forceinline__ void cp_commit() {
    asm volatile("cp.async.commit_group;\n");
}
template<int N>
__device__ __forceinline__ void cp_wait() {
    asm volatile("cp.async.wait_group %0;\n" :: "n"(N));
}
__device__ __forceinline__ void ldm4(unsigned* r, const __half* p) {
    unsigned a = s2u(p);
    asm volatile("ldmatrix.sync.aligned.m8n8.x4.shared.b16 {%0,%1,%2,%3}, [%4];"
        : "=r"(r[0]), "=r"(r[1]), "=r"(r[2]), "=r"(r[3]) : "r"(a));
}
__device__ __forceinline__ void mma16816(float* c, const unsigned* a, unsigned b0, unsigned b1) {
    asm volatile(
        "mma.sync.aligned.m16n8k16.row.col.f32.f16.f16.f32 "
        "{%0,%1,%2,%3},{%4,%5,%6,%7},{%8,%9},{%0,%1,%2,%3};"
        : "+f"(c[0]), "+f"(c[1]), "+f"(c[2]), "+f"(c[3])
        : "r"(a[0]), "r"(a[1]), "r"(a[2]), "r"(a[3]), "r"(b0), "r"(b1));
}
// swizzled index (half units) in a [rows][32] k-major half tile
__device__ __forceinline__ int swzh(int r, int k) {
    return r*32 + ((((k >> 3) ^ ((r >> 1) & 3)) << 3) | (k & 7));
}
__device__ __forceinline__ float logaddexpf(float a, float b) {
    float mx = fmaxf(a, b), mn = fminf(a, b);
    return mx + log1pf(expf(mn - mx));
}

// ---------------- weight prep: transpose + convert (wide stores) ----------
// src: [z][R][Cc] fp32 -> dst: [z][Cc][R] half.  Tile: 64 R-rows x 32 Cc-cols.
__global__ __launch_bounds__(256) void tconv_k(const float* __restrict__ src,
                                               __half* __restrict__ dst, int R, int Cc)
{
    __shared__ float t[64][33];
    int c0 = blockIdx.x*32, r0 = blockIdx.y*64, z = blockIdx.z;
    src += (size_t)z*R*Cc;
    dst += (size_t)z*R*Cc;
    int tx = threadIdx.x, ty = threadIdx.y;   // 32 x 8
    #pragma unroll
    for (int i = 0; i < 8; i++)
        t[ty + 8*i][tx] = src[(size_t)(r0 + ty + 8*i)*Cc + c0 + tx];
    __syncthreads();
    int tid = ty*32 + tx;
    int cc = tid >> 3, w = tid & 7;
    __half* orow = dst + (size_t)(c0 + cc)*R + r0;
    #pragma unroll
    for (int sb = 0; sb < 2; sb++) {
        int s = w + sb*8;
        __half2 h[2];
        h[0] = __floats2half2_rn(t[4*s  ][cc], t[4*s+1][cc]);
        h[1] = __floats2half2_rn(t[4*s+2][cc], t[4*s+3][cc]);
        *(uint2*)&orow[4*s] = *(uint2*)h;
    }
}
// straight convert fp32 -> half (float4 in, 8B out)
__global__ __launch_bounds__(256) void conv_k(const float* __restrict__ src,
                                              __half* __restrict__ dst, size_t n4)
{
    size_t stride = (size_t)gridDim.x * blockDim.x;
    for (size_t i = (size_t)blockIdx.x*blockDim.x + threadIdx.x; i < n4; i += stride) {
        float4 v = ((const float4*)src)[i];
        __half2 h[2];
        h[0] = __floats2half2_rn(v.x, v.y);
        h[1] = __floats2half2_rn(v.z, v.w);
        ((uint2*)dst)[i] = *(uint2*)h;
    }
}

// ---------------- embedding gather (fp32 + half) --------------------------
__global__ void embed_k(const int* __restrict__ tok, const float* __restrict__ ew,
                        float* __restrict__ x, __half* __restrict__ xh) {
    int s = blockIdx.x;
    int t = tok[s];
    for (int d = threadIdx.x; d < D; d += blockDim.x) {
        float v = ew[(size_t)t*D + d];
        x[(size_t)s*D + d] = v;
        xh[(size_t)s*D + d] = __float2half_rn(v);
    }
}

// ---------------- fp16 tensor-core GEMM (4-stage cp.async, NT only) -------
// C(MxN) fp32 = A_h(MxK) @ B_h(NxK)^T (+bias +res).
#define NSTG 4

template<int WGM, int WGN, int SMc, int SNc>
__global__ __launch_bounds__(WGM*WGN*32) void hgemm(
    const __half* __restrict__ A, const __half* __restrict__ B,
    const float* __restrict__ bias, const float* __restrict__ res,
    float* __restrict__ C, int M, int N, int K)
{
    constexpr int BM = WGM*SMc*16, BN = WGN*SNc*16, NT = WGM*WGN*32;
    constexpr int ASZ = BM*32, BSZ = BN*32;   // halfs per stage

    extern __shared__ __half sh[];
    __half* Asm = sh;
    __half* Bsm = sh + NSTG*ASZ;

    const int tid  = threadIdx.x;
    const int wid  = tid >> 5, lane = tid & 31;
    const int g    = lane >> 2, tg = lane & 3;
    const int r15  = lane & 15, khi = (lane >> 4) * 8;
    const int m0   = blockIdx.x * BM, n0 = blockIdx.y * BN;
    const int wm0  = (wid / WGN) * (SMc*16);
    const int wn0  = (wid % WGN) * (SNc*16);

    float acc[SMc][2*SNc][4] = {};

    auto load_stage = [&](int t) {
        const int k0 = t * 32;
        __half* As = Asm + (t & (NSTG-1))*ASZ;
        __half* Bs = Bsm + (t & (NSTG-1))*BSZ;
        #pragma unroll
        for (int cl = tid; cl < BM*4; cl += NT) {
            int m = cl >> 2, c = cl & 3;
            cp16(s2u(&As[m*32 + ((c ^ ((m>>1)&3)) << 3)]),
                 &A[(size_t)(m0 + m)*K + k0 + c*8]);
        }
        #pragma unroll
        for (int cl = tid; cl < BN*4; cl += NT) {
            int n = cl >> 2, c = cl & 3;
            cp16(s2u(&Bs[n*32 + ((c ^ ((n>>1)&3)) << 3)]),
                 &B[(size_t)(n0 + n)*K + k0 + c*8]);
        }
        cp_commit();
    };

    auto compute = [&](int t) {
        const __half* As = Asm + (t & (NSTG-1))*ASZ;
        const __half* Bs = Bsm + (t & (NSTG-1))*BSZ;
        #pragma unroll
        for (int kk = 0; kk < 2; kk++) {
            unsigned af[SMc][4], bf[SNc][4];
            #pragma unroll
            for (int i = 0; i < SMc; i++)
                ldm4(af[i], &As[swzh(wm0 + i*16 + r15, kk*16 + khi)]);
            #pragma unroll
            for (int j = 0; j < SNc; j++)
                ldm4(bf[j], &Bs[swzh(wn0 + j*16 + r15, kk*16 + khi)]);
            #pragma unroll
            for (int i = 0; i < SMc; i++)
                #pragma unroll
                for (int j = 0; j < SNc; j++) {
                    mma16816(acc[i][2*j  ], af[i], bf[j][0], bf[j][2]);
                    mma16816(acc[i][2*j+1], af[i], bf[j][1], bf[j][3]);
                }
        }
    };

    // Single barrier per iteration is safe: the barrier at iter t is passed only
    // after all warps finished compute(t-1); load_stage(t+3) writes slot (t-1)&3,
    // whose last reader was compute(t-1).
    const int NIT = K / 32;    // 24 at every call site
    load_stage(0); load_stage(1); load_stage(2);
    for (int t = 0; t < NIT; t++) {
        if (t < NIT-2)       cp_wait<2>();
        else if (t == NIT-2) cp_wait<1>();
        else                 cp_wait<0>();
        __syncthreads();
        if (t + 3 < NIT) load_stage(t + 3);
        compute(t);
    }

    // ---- epilogue (fp32) ----
    #pragma unroll
    for (int i = 0; i < SMc; i++) {
        int mA = m0 + wm0 + i*16 + g;
        #pragma unroll
        for (int jj = 0; jj < 2*SNc; jj++) {
            int col = n0 + wn0 + (jj >> 1)*16 + (jj & 1)*8 + 2*tg;
            float b0 = bias ? bias[col] : 0.0f, b1 = bias ? bias[col+1] : 0.0f;
            float v0 = acc[i][jj][0] + b0, v1 = acc[i][jj][1] + b1;
            float v2 = acc[i][jj][2] + b0, v3 = acc[i][jj][3] + b1;
            if (res) {
                v0 += res[(size_t)mA*N + col];     v1 += res[(size_t)mA*N + col+1];
                v2 += res[(size_t)(mA+8)*N + col]; v3 += res[(size_t)(mA+8)*N + col+1];
            }
            *(float2*)&C[(size_t)mA*N + col]     = make_float2(v0, v1);
            *(float2*)&C[(size_t)(mA+8)*N + col] = make_float2(v2, v3);
        }
    }
}

// ---------------- fused ff1 + GLU GEMM (occupancy-tuned) -------------------
__global__ __launch_bounds__(128) void hgemm_glu(
    const __half* __restrict__ A, const __half* __restrict__ B,
    const float* __restrict__ bias, __half* __restrict__ O, int K)
{
    constexpr int BM = 64, BN = 64, NT = 128;
    constexpr int ASZ = BM*32, BSZ = 2*BN*32;

    extern __shared__ __half sh[];
    __half* Asm = sh;
    __half* Bsm = sh + NSTG*ASZ;

    const int tid  = threadIdx.x;
    const int wid  = tid >> 5, lane = tid & 31;
    const int g    = lane >> 2, tg = lane & 3;
    const int r15  = lane & 15, khi = (lane >> 4) * 8;
    const int m0   = blockIdx.x * BM, n0 = blockIdx.y * BN;
    const int wm0  = (wid >> 1) * 32;
    const int wn0  = (wid & 1) * 32;

    float accA[2][4][4] = {}, accB[2][4][4] = {};

    auto load_stage = [&](int t) {
        const int k0 = t * 32;
        __half* As = Asm + (t & (NSTG-1))*ASZ;
        __half* Bs = Bsm + (t & (NSTG-1))*BSZ;
        #pragma unroll
        for (int cl = tid; cl < BM*4; cl += NT) {
            int m = cl >> 2, c = cl & 3;
            cp16(s2u(&As[m*32 + ((c ^ ((m>>1)&3)) << 3)]),
                 &A[(size_t)(m0 + m)*K + k0 + c*8]);
        }
        #pragma unroll
        for (int cl = tid; cl < 2*BN*4; cl += NT) {
            int n = cl >> 2, c = cl & 3;
            int gr = (n < BN) ? (n0 + n) : (D + n0 + (n - BN));
            cp16(s2u(&Bs[n*32 + ((c ^ ((n>>1)&3)) << 3)]),
                 &B[(size_t)gr*K + k0 + c*8]);
        }
        cp_commit();
    };

    auto compute = [&](int t) {
        const __half* As = Asm + (t & (NSTG-1))*ASZ;
        const __half* Bs = Bsm + (t & (NSTG-1))*BSZ;
        #pragma unroll
        for (int kk = 0; kk < 2; kk++) {
            unsigned af[2][4], bf1[2][4], bf2[2][4];
            #pragma unroll
            for (int i = 0; i < 2; i++)
                ldm4(af[i], &As[swzh(wm0 + i*16 + r15, kk*16 + khi)]);
            #pragma unroll
            for (int j = 0; j < 2; j++) {
                ldm4(bf1[j], &Bs[swzh(wn0 + j*16 + r15,      kk*16 + khi)]);
                ldm4(bf2[j], &Bs[swzh(BN + wn0 + j*16 + r15, kk*16 + khi)]);
            }
            #pragma unroll
            for (int i = 0; i < 2; i++)
                #pragma unroll
                for (int j = 0; j < 2; j++) {
                    mma16816(accA[i][2*j  ], af[i], bf1[j][0], bf1[j][2]);
                    mma16816(accA[i][2*j+1], af[i], bf1[j][1], bf1[j][3]);
                    mma16816(accB[i][2*j  ], af[i], bf2[j][0], bf2[j][2]);
                    mma16816(accB[i][2*j+1], af[i], bf2[j][1], bf2[j][3]);
                }
        }
    };

    const int NIT = K / 32;
    load_stage(0); load_stage(1); load_stage(2);
    for (int t = 0; t < NIT; t++) {
        if (t < NIT-2)       cp_wait<2>();
        else if (t == NIT-2) cp_wait<1>();
        else                 cp_wait<0>();
        __syncthreads();
        if (t + 3 < NIT) load_stage(t + 3);
        compute(t);
    }

    // ---- epilogue: GLU, half out ----
    #pragma unroll
    for (int i = 0; i < 2; i++) {
        int mA = m0 + wm0 + i*16 + g;
        #pragma unroll
        for (int jj = 0; jj < 4; jj++) {
            int col = n0 + wn0 + (jj >> 1)*16 + (jj & 1)*8 + 2*tg;
            float b10 = bias[col], b11 = bias[col+1];
            float b20 = bias[D+col], b21 = bias[D+col+1];
            float z10 = accA[i][jj][0] + b10, z11 = accA[i][jj][1] + b11;
            float z12 = accA[i][jj][2] + b10, z13 = accA[i][jj][3] + b11;
            float z20 = accB[i][jj][0] + b20, z21 = accB[i][jj][1] + b21;
            float z22 = accB[i][jj][2] + b20, z23 = accB[i][jj][3] + b21;
            float o0 = z10 * (1.0f/(1.0f+expf(-z20)));
            float o1 = z11 * (1.0f/(1.0f+expf(-z21)));
            float o2 = z12 * (1.0f/(1.0f+expf(-z22)));
            float o3 = z13 * (1.0f/(1.0f+expf(-z23)));
            *(__half2*)&O[(size_t)mA*D + col]     = __floats2half2_rn(o0, o1);
            *(__half2*)&O[(size_t)(mA+8)*D + col] = __floats2half2_rn(o2, o3);
        }
    }
}

// ---------------- layernorm: one warp per row ------------------------------
__global__ __launch_bounds__(256) void ln_k(const float* __restrict__ x,
    const float* __restrict__ g, const float* __restrict__ b, __half* __restrict__ y)
{
    int warp = threadIdx.x >> 5, lane = threadIdx.x & 31;
    int s = blockIdx.x*8 + warp;
    const float* row = x + (size_t)s*D + lane*24;
    float v[24];
    #pragma unroll
    for (int j = 0; j < 6; j++) {
        float4 t = *(const float4*)(row + j*4);
        v[4*j] = t.x; v[4*j+1] = t.y; v[4*j+2] = t.z; v[4*j+3] = t.w;
    }
    float sum = 0.0f;
    #pragma unroll
    for (int i = 0; i < 24; i++) sum += v[i];
    #pragma unroll
    for (int o = 16; o > 0; o >>= 1) sum += __shfl_xor_sync(0xffffffffu, sum, o);
    float mean = sum * (1.0f/768.0f);
    float vs = 0.0f;
    #pragma unroll
    for (int i = 0; i < 24; i++) { float d = v[i] - mean; vs += d*d; }
    #pragma unroll
    for (int o = 16; o > 0; o >>= 1) vs += __shfl_xor_sync(0xffffffffu, vs, o);
    float inv = rsqrtf(vs * (1.0f/768.0f) + 1e-5f);
    const float* gp = g + lane*24;
    const float* bp = b + lane*24;
    __half hb[24];
    #pragma unroll
    for (int j = 0; j < 6; j++) {
        float4 gg = *(const float4*)(gp + j*4);
        float4 bb = *(const float4*)(bp + j*4);
        hb[4*j  ] = __float2half_rn((v[4*j  ]-mean)*inv*gg.x + bb.x);
        hb[4*j+1] = __float2half_rn((v[4*j+1]-mean)*inv*gg.y + bb.y);
        hb[4*j+2] = __float2half_rn((v[4*j+2]-mean)*inv*gg.z + bb.z);
        hb[4*j+3] = __float2half_rn((v[4*j+3]-mean)*inv*gg.w + bb.w);
    }
    __half* orow = y + (size_t)s*D + lane*24;
    #pragma unroll
    for (int j = 0; j < 3; j++)
        *(uint4*)&orow[8*j] = *(uint4*)&hb[8*j];
}

// ---------------- position scan (chunked 3-pass) ---------------------------
// pass 1: per (d, chunk): chunk-local sum of log_coeffs + local LSE of (lg - local_acc)
__global__ __launch_bounds__(256) void ps1_k(const float* __restrict__ h,
    float* __restrict__ psum, float* __restrict__ plse)
{
    int d = blockIdx.x*256 + threadIdx.x;
    int c = blockIdx.y;
    float acc = 0.0f, lse = -__int_as_float(0x7f800000);  // -inf
    for (int t = 0; t < 32; t++) {
        int s = c*32 + t;
        float hv = h[(size_t)s*(2*D) + d];
        float lg = h[(size_t)s*(2*D) + D + d];
        float lc = (hv >= 0.0f) ? (-log1pf(expf(-hv))) : (hv - log1pf(expf(hv)));
        acc += lc;
        lse = logaddexpf(lse, lg - acc);
    }
    psum[c*D + d] = acc;
    plse[c*D + d] = lse;
}
// pass 2: per d: exclusive prefixes over chunks (acc base + running logaddexp incl pad-0)
__global__ __launch_bounds__(256) void ps2_k(const float* __restrict__ psum,
    const float* __restrict__ plse, float* __restrict__ accb, float* __restrict__ Rarr)
{
    int d = blockIdx.x*256 + threadIdx.x;
    float ab = 0.0f, R = 0.0f;    // R starts at 0: the padded t=-1 term
    for (int c = 0; c < NCH; c++) {
        accb[c*D + d] = ab;
        Rarr[c*D + d] = R;
        R = logaddexpf(R, plse[c*D + d] - ab);
        ab += psum[c*D + d];
    }
}
// pass 3: per (d, chunk): recompute local scan, add carry, write x += out
__global__ __launch_bounds__(256) void ps3_k(const float* __restrict__ h,
    const float* __restrict__ accb, const float* __restrict__ Rarr,
    float* __restrict__ x)
{
    int d = blockIdx.x*256 + threadIdx.x;
    int c = blockIdx.y;
    float ab = accb[c*D + d], R = Rarr[c*D + d];
    float acc = 0.0f, lse = -__int_as_float(0x7f800000);
    for (int t = 0; t < 32; t++) {
        int s = c*32 + t;
        float hv = h[(size_t)s*(2*D) + d];
        float lg = h[(size_t)s*(2*D) + D + d];
        float lc = (hv >= 0.0f) ? (-log1pf(expf(-hv))) : (hv - log1pf(expf(hv)));
        acc += lc;
        lse = logaddexpf(lse, lg - acc);
        float out = (ab + acc) + logaddexpf(R, lse - ab);
        x[(size_t)s*D + d] += out;
    }
}

// ---------------- attention pass A: per-chunk sums -------------------------
__global__ __launch_bounds__(1024) void attnA_k(const float* __restrict__ qkv,
    float* __restrict__ Asum, float* __restrict__ Zsum)
{
    int c = blockIdx.x, hh = blockIdx.y;
    int tid = threadIdx.x, lane = tid & 31, wid = tid >> 5;
    __shared__ float ek[CT][33], ev[CT][33];
    const float* base = qkv + (size_t)(c*CT + wid)*QKV_N + hh*96;
    ek[wid][lane] = expf(base[32 + lane]);
    ev[wid][lane] = expf(base[64 + lane]);
    __syncthreads();
    float m = 0.0f;
    #pragma unroll
    for (int t = 0; t < CT; t++) m = fmaf(ek[t][wid], ev[t][lane], m);
    Asum[(size_t)(((hh*NCH)+c)*DKV + wid)*DKV + lane] = m;
    if (wid == 0) {
        float z = 0.0f;
        #pragma unroll
        for (int t = 0; t < CT; t++) z += ek[t][lane];
        Zsum[(size_t)((hh*NCH)+c)*DKV + lane] = z;
    }
}

// ---------------- attention pass C: carry-from-Asum + intra-chunk ----------
__global__ __launch_bounds__(1024) void attnC_k(const float* __restrict__ qkv,
    const float* __restrict__ Asum, const float* __restrict__ Zsum,
    __half* __restrict__ att)
{
    int c = blockIdx.x, hh = blockIdx.y;
    int tid = threadIdx.x, lane = tid & 31, wid = tid >> 5;
    __shared__ float eq[CT][33], ek[CT][33], ev[CT][33], P[CT][33], M0[DKV][33];
    __shared__ float z0[DKV];
    const float* base = qkv + (size_t)(c*CT + wid)*QKV_N + hh*96;
    eq[wid][lane] = expf(base[      lane]);
    ek[wid][lane] = expf(base[32 +  lane]);
    ev[wid][lane] = expf(base[64 +  lane]);
    {
        float m0 = 0.0f;
        for (int cc = 0; cc < c; cc++)
            m0 += Asum[(size_t)(((hh*NCH)+cc)*DKV + wid)*DKV + lane];
        M0[wid][lane] = m0;
    }
    if (tid < DKV) {
        float z = 0.0f;
        for (int cc = 0; cc < c; cc++)
            z += Zsum[(size_t)((hh*NCH)+cc)*DKV + tid];
        z0[tid] = z;
    }
    __syncthreads();
    float p = 0.0f;
    #pragma unroll
    for (int k = 0; k < DKV; k++) p = fmaf(eq[wid][k], ek[lane][k], p);
    P[wid][lane] = p;
    __syncthreads();
    float num = 0.0f, den = 0.0f;
    #pragma unroll
    for (int k = 0; k < DKV; k++) {
        float q = eq[wid][k];
        num = fmaf(q, M0[k][lane], num);
        den = fmaf(q, z0[k], den);
    }
    for (int s2 = 0; s2 <= wid; s2++) {
        float ps = P[wid][s2];
        num = fmaf(ps, ev[s2][lane], num);
        den += ps;
    }
    att[(size_t)(c*CT + wid)*D + hh*DKV + lane] = __float2half_rn(logf(num) - logf(den));
}

// ---------------- launcher -----------------------------------------------
extern "C" void kernel_launch(void* const* d_in, const int* in_sizes, int n_in,
                              void* d_out, int out_size)
{
    const int*   tok  = (const int*)  d_in[0];
    const float* embw = (const float*)d_in[1];
    const float* posw = (const float*)d_in[2];
    const float* posb = (const float*)d_in[3];
    const float* ln1g = (const float*)d_in[4];
    const float* ln1b = (const float*)d_in[5];
    const float* qkvw = (const float*)d_in[6];
    const float* qkvb = (const float*)d_in[7];
    const float* ffw1 = (const float*)d_in[8];
    const float* ffb1 = (const float*)d_in[9];
    const float* ffw2 = (const float*)d_in[10];
    const float* lnfg = (const float*)d_in[11];
    const float* lnfb = (const float*)d_in[12];
    float* out = (float*)d_out;

    float *x,*hh,*qkv,*Asum,*Zsum,*psum,*plse,*paccb,*pR;
    __half *xh,*xnh,*atth,*gluh,*poswh,*qkvwh,*ff1wh,*ff2wh,*embwh;
    cudaGetSymbolAddress((void**)&x,    g_x);
    cudaGetSymbolAddress((void**)&hh,   g_h);
    cudaGetSymbolAddress((void**)&qkv,  g_qkv);
    cudaGetSymbolAddress((void**)&Asum, g_Asum);
    cudaGetSymbolAddress((void**)&Zsum, g_Zsum);
    cudaGetSymbolAddress((void**)&psum, g_ps_sum);
    cudaGetSymbolAddress((void**)&plse, g_ps_lse);
    cudaGetSymbolAddress((void**)&paccb,g_ps_accb);
    cudaGetSymbolAddress((void**)&pR,   g_ps_R);
    cudaGetSymbolAddress((void**)&xh,    g_xh);
    cudaGetSymbolAddress((void**)&xnh,   g_xnh);
    cudaGetSymbolAddress((void**)&atth,  g_atth);
    cudaGetSymbolAddress((void**)&gluh,  g_gluh);
    cudaGetSymbolAddress((void**)&poswh, g_poswh);
    cudaGetSymbolAddress((void**)&qkvwh, g_qkvwh);
    cudaGetSymbolAddress((void**)&ff1wh, g_ff1wh);
    cudaGetSymbolAddress((void**)&ff2wh, g_ff2wh);
    cudaGetSymbolAddress((void**)&embwh, g_embwh);

    // smem per config: NSTG*(BM+BN)*32 halfs
    const int sm_A = NSTG*( 64+128)*32*2;   // 49152  (64x128, pos/qkv)
    const int sm_B = NSTG*( 64+ 64)*32*2;   // 32768  (64x64,  ff2)
    const int sm_C = NSTG*(128+128)*32*2;   // 65536  (128x128, logits)
    const int sm_G = NSTG*( 64+128)*32*2;   // 49152  (ff1+glu dual 64-panel)
    cudaFuncSetAttribute(hgemm<2,4,2,2>, cudaFuncAttributeMaxDynamicSharedMemorySize, sm_A);
    cudaFuncSetAttribute(hgemm<2,2,2,2>, cudaFuncAttributeMaxDynamicSharedMemorySize, sm_B);
    cudaFuncSetAttribute(hgemm<2,4,4,2>, cudaFuncAttributeMaxDynamicSharedMemorySize, sm_C);
    cudaFuncSetAttribute(hgemm_glu,      cudaFuncAttributeMaxDynamicSharedMemorySize, sm_G);

    // ---- weight prep (every call; deterministic) ----
    tconv_k<<<dim3(2*D/32,  D/64, 1     ), dim3(32,8)>>>(posw, poswh, D, 2*D);
    tconv_k<<<dim3(QKV_N/32,D/64, LAYERS), dim3(32,8)>>>(qkvw, qkvwh, D, QKV_N);
    tconv_k<<<dim3(FF_N/32, D/64, LAYERS), dim3(32,8)>>>(ffw1, ff1wh, D, FF_N);
    tconv_k<<<dim3(D/32,    D/64, LAYERS), dim3(32,8)>>>(ffw2, ff2wh, D, D);
    conv_k<<<1024, 256>>>(embw, embwh, (size_t)VSZ*D/4);

    // ---- embed + position recurrence ----
    embed_k<<<S, 256>>>(tok, embw, x, xh);
    hgemm<2,4,2,2><<<dim3(S/64, 2*D/128), 256, sm_A>>>(
        xh, poswh, posb, nullptr, hh, S, 2*D, D);
    ps1_k<<<dim3(3, NCH), 256>>>(hh, psum, plse);
    ps2_k<<<3, 256>>>(psum, plse, paccb, pR);
    ps3_k<<<dim3(3, NCH), 256>>>(hh, paccb, pR, x);

    for (int l = 0; l < LAYERS; l++) {
        ln_k<<<S/8, 256>>>(x, ln1g + (size_t)l*D, ln1b + (size_t)l*D, xnh);
        hgemm<2,4,2,2><<<dim3(S/64, QKV_N/128), 256, sm_A>>>(
            xnh, qkvwh + (size_t)l*D*QKV_N, qkvb + (size_t)l*QKV_N, nullptr, qkv, S, QKV_N, D);
        attnA_k<<<dim3(NCH, HEADS), 1024>>>(qkv, Asum, Zsum);
        attnC_k<<<dim3(NCH, HEADS), 1024>>>(qkv, Asum, Zsum, atth);
        hgemm_glu<<<dim3(S/64, D/64), 128, sm_G>>>(
            atth, ff1wh + (size_t)l*D*FF_N, ffb1 + (size_t)l*FF_N, gluh, D);
        hgemm<2,2,2,2><<<dim3(S/64, D/64), 128, sm_B>>>(
            gluh, ff2wh + (size_t)l*D*D, nullptr, x, x, S, D, D);
    }

    ln_k<<<S/8, 256>>>(x, lnfg, lnfb, xnh);
    hgemm<2,4,4,2><<<dim3(S/128, VSZ/128), 256, sm_C>>>(
        xnh, embwh, nullptr, nullptr, out, S, VSZ, D);
}

// round 15
// speedup vs baseline: 1.4677x; 1.0162x over previous
#include <cuda_runtime.h>
#include <cuda_fp16.h>
#include <math.h>

#define S 1024
#define D 768
#define LAYERS 12
#define HEADS 24
#define DKV 32
#define QKV_N 2304
#define FF_N 1536
#define VSZ 50304
#define NCH 32
#define CT 32

// ---------------- scratch -----------------------------------------------
__device__ float g_x[S*D];
__device__ float g_h[S*2*D];
__device__ float g_qkv[S*QKV_N];
__device__ float g_Asum[HEADS*NCH*DKV*DKV];
__device__ float g_Zsum[HEADS*NCH*DKV];
__device__ float g_Mcar[HEADS*NCH*DKV*DKV];
__device__ float g_Zcar[HEADS*NCH*DKV];
__device__ float g_ps_sum[NCH*D];
__device__ float g_ps_lse[NCH*D];
__device__ float g_ps_accb[NCH*D];
__device__ float g_ps_R[NCH*D];

__device__ __half g_xh[S*D];
__device__ __half g_xnh[S*D];
__device__ __half g_atth[S*D];
__device__ __half g_gluh[S*D];
__device__ __half g_poswh[D*2*D];
__device__ __half g_qkvwh[LAYERS*D*QKV_N];
__device__ __half g_ff1wh[LAYERS*D*FF_N];
__device__ __half g_ff2wh[LAYERS*D*D];
__device__ __half g_embwh[(size_t)VSZ*D];

// ---------------- low-level helpers --------------------------------------
__device__ __forceinline__ unsigned s2u(const void* p) {
    return (unsigned)__cvta_generic_to_shared(p);
}
__device__ __forceinline__ void cp16(unsigned dst, const void* src) {
    asm volatile("cp.async.cg.shared.global [%0], [%1], 16;\n" :: "r"(dst), "l"(src));
}
__device__ __forceinline__ void cp_commit() {
    asm volatile("cp.async.commit_group;\n");
}
template<int N>
__device__ __forceinline__ void cp_wait() {
    asm volatile("cp.async.wait_group %0;\n" :: "n"(N));
}
__device__ __forceinline__ void ldm4(unsigned* r, const __half* p) {
    unsigned a = s2u(p);
    asm volatile("ldmatrix.sync.aligned.m8n8.x4.shared.b16 {%0,%1,%2,%3}, [%4];"
        : "=r"(r[0]), "=r"(r[1]), "=r"(r[2]), "=r"(r[3]) : "r"(a));
}
__device__ __forceinline__ void mma16816(float* c, const unsigned* a, unsigned b0, unsigned b1) {
    asm volatile(
        "mma.sync.aligned.m16n8k16.row.col.f32.f16.f16.f32 "
        "{%0,%1,%2,%3},{%4,%5,%6,%7},{%8,%9},{%0,%1,%2,%3};"
        : "+f"(c[0]), "+f"(c[1]), "+f"(c[2]), "+f"(c[3])
        : "r"(a[0]), "r"(a[1]), "r"(a[2]), "r"(a[3]), "r"(b0), "r"(b1));
}
// swizzled index (half units) in a [rows][32] k-major half tile
__device__ __forceinline__ int swzh(int r, int k) {
    return r*32 + ((((k >> 3) ^ ((r >> 1) & 3)) << 3) | (k & 7));
}
__device__ __forceinline__ float logaddexpf(float a, float b) {
    float mx = fmaxf(a, b), mn = fminf(a, b);
    return mx + log1pf(expf(mn - mx));
}

// ---------------- weight prep: transpose + convert (wide stores) ----------
__global__ __launch_bounds__(256) void tconv_k(const float* __restrict__ src,
                                               __half* __restrict__ dst, int R, int Cc)
{
    __shared__ float t[64][33];
    int c0 = blockIdx.x*32, r0 = blockIdx.y*64, z = blockIdx.z;
    src += (size_t)z*R*Cc;
    dst += (size_t)z*R*Cc;
    int tx = threadIdx.x, ty = threadIdx.y;   // 32 x 8
    #pragma unroll
    for (int i = 0; i < 8; i++)
        t[ty + 8*i][tx] = src[(size_t)(r0 + ty + 8*i)*Cc + c0 + tx];
    __syncthreads();
    int tid = ty*32 + tx;
    int cc = tid >> 3, w = tid & 7;
    __half* orow = dst + (size_t)(c0 + cc)*R + r0;
    #pragma unroll
    for (int sb = 0; sb < 2; sb++) {
        int s = w + sb*8;
        __half2 h[2];
        h[0] = __floats2half2_rn(t[4*s  ][cc], t[4*s+1][cc]);
        h[1] = __floats2half2_rn(t[4*s+2][cc], t[4*s+3][cc]);
        *(uint2*)&orow[4*s] = *(uint2*)h;
    }
}
__global__ __launch_bounds__(256) void conv_k(const float* __restrict__ src,
                                              __half* __restrict__ dst, size_t n4)
{
    size_t stride = (size_t)gridDim.x * blockDim.x;
    for (size_t i = (size_t)blockIdx.x*blockDim.x + threadIdx.x; i < n4; i += stride) {
        float4 v = ((const float4*)src)[i];
        __half2 h[2];
        h[0] = __floats2half2_rn(v.x, v.y);
        h[1] = __floats2half2_rn(v.z, v.w);
        ((uint2*)dst)[i] = *(uint2*)h;
    }
}

// ---------------- embedding gather (fp32 + half) --------------------------
__global__ void embed_k(const int* __restrict__ tok, const float* __restrict__ ew,
                        float* __restrict__ x, __half* __restrict__ xh) {
    int s = blockIdx.x;
    int t = tok[s];
    for (int d = threadIdx.x; d < D; d += blockDim.x) {
        float v = ew[(size_t)t*D + d];
        x[(size_t)s*D + d] = v;
        xh[(size_t)s*D + d] = __float2half_rn(v);
    }
}

// ---------------- fp16 tensor-core GEMM (4-stage cp.async, NT only) -------
#define NSTG 4

template<int WGM, int WGN, int SMc, int SNc>
__global__ __launch_bounds__(WGM*WGN*32) void hgemm(
    const __half* __restrict__ A, const __half* __restrict__ B,
    const float* __restrict__ bias, const float* __restrict__ res,
    float* __restrict__ C, int M, int N, int K)
{
    constexpr int BM = WGM*SMc*16, BN = WGN*SNc*16, NT = WGM*WGN*32;
    constexpr int ASZ = BM*32, BSZ = BN*32;

    extern __shared__ __half sh[];
    __half* Asm = sh;
    __half* Bsm = sh + NSTG*ASZ;

    const int tid  = threadIdx.x;
    const int wid  = tid >> 5, lane = tid & 31;
    const int g    = lane >> 2, tg = lane & 3;
    const int r15  = lane & 15, khi = (lane >> 4) * 8;
    const int m0   = blockIdx.x * BM, n0 = blockIdx.y * BN;
    const int wm0  = (wid / WGN) * (SMc*16);
    const int wn0  = (wid % WGN) * (SNc*16);

    float acc[SMc][2*SNc][4] = {};

    auto load_stage = [&](int t) {
        const int k0 = t * 32;
        __half* As = Asm + (t & (NSTG-1))*ASZ;
        __half* Bs = Bsm + (t & (NSTG-1))*BSZ;
        #pragma unroll
        for (int cl = tid; cl < BM*4; cl += NT) {
            int m = cl >> 2, c = cl & 3;
            cp16(s2u(&As[m*32 + ((c ^ ((m>>1)&3)) << 3)]),
                 &A[(size_t)(m0 + m)*K + k0 + c*8]);
        }
        #pragma unroll
        for (int cl = tid; cl < BN*4; cl += NT) {
            int n = cl >> 2, c = cl & 3;
            cp16(s2u(&Bs[n*32 + ((c ^ ((n>>1)&3)) << 3)]),
                 &B[(size_t)(n0 + n)*K + k0 + c*8]);
        }
        cp_commit();
    };

    auto compute = [&](int t) {
        const __half* As = Asm + (t & (NSTG-1))*ASZ;
        const __half* Bs = Bsm + (t & (NSTG-1))*BSZ;
        #pragma unroll
        for (int kk = 0; kk < 2; kk++) {
            unsigned af[SMc][4], bf[SNc][4];
            #pragma unroll
            for (int i = 0; i < SMc; i++)
                ldm4(af[i], &As[swzh(wm0 + i*16 + r15, kk*16 + khi)]);
            #pragma unroll
            for (int j = 0; j < SNc; j++)
                ldm4(bf[j], &Bs[swzh(wn0 + j*16 + r15, kk*16 + khi)]);
            #pragma unroll
            for (int i = 0; i < SMc; i++)
                #pragma unroll
                for (int j = 0; j < SNc; j++) {
                    mma16816(acc[i][2*j  ], af[i], bf[j][0], bf[j][2]);
                    mma16816(acc[i][2*j+1], af[i], bf[j][1], bf[j][3]);
                }
        }
    };

    // Single barrier per iteration (validated round 14): barrier at iter t is
    // passed only after all warps finished compute(t-1); load_stage(t+3)
    // writes slot (t-1)&3 whose last reader was compute(t-1).
    const int NIT = K / 32;
    load_stage(0); load_stage(1); load_stage(2);
    for (int t = 0; t < NIT; t++) {
        if (t < NIT-2)       cp_wait<2>();
        else if (t == NIT-2) cp_wait<1>();
        else                 cp_wait<0>();
        __syncthreads();
        if (t + 3 < NIT) load_stage(t + 3);
        compute(t);
    }

    // ---- epilogue (fp32) ----
    #pragma unroll
    for (int i = 0; i < SMc; i++) {
        int mA = m0 + wm0 + i*16 + g;
        #pragma unroll
        for (int jj = 0; jj < 2*SNc; jj++) {
            int col = n0 + wn0 + (jj >> 1)*16 + (jj & 1)*8 + 2*tg;
            float b0 = bias ? bias[col] : 0.0f, b1 = bias ? bias[col+1] : 0.0f;
            float v0 = acc[i][jj][0] + b0, v1 = acc[i][jj][1] + b1;
            float v2 = acc[i][jj][2] + b0, v3 = acc[i][jj][3] + b1;
            if (res) {
                v0 += res[(size_t)mA*N + col];     v1 += res[(size_t)mA*N + col+1];
                v2 += res[(size_t)(mA+8)*N + col]; v3 += res[(size_t)(mA+8)*N + col+1];
            }
            *(float2*)&C[(size_t)mA*N + col]     = make_float2(v0, v1);
            *(float2*)&C[(size_t)(mA+8)*N + col] = make_float2(v2, v3);
        }
    }
}

// ---------------- fused ff1 + GLU GEMM (occupancy-tuned) -------------------
__global__ __launch_bounds__(128) void hgemm_glu(
    const __half* __restrict__ A, const __half* __restrict__ B,
    const float* __restrict__ bias, __half* __restrict__ O, int K)
{
    constexpr int BM = 64, BN = 64, NT = 128;
    constexpr int ASZ = BM*32, BSZ = 2*BN*32;

    extern __shared__ __half sh[];
    __half* Asm = sh;
    __half* Bsm = sh + NSTG*ASZ;

    const int tid  = threadIdx.x;
    const int wid  = tid >> 5, lane = tid & 31;
    const int g    = lane >> 2, tg = lane & 3;
    const int r15  = lane & 15, khi = (lane >> 4) * 8;
    const int m0   = blockIdx.x * BM, n0 = blockIdx.y * BN;
    const int wm0  = (wid >> 1) * 32;
    const int wn0  = (wid & 1) * 32;

    float accA[2][4][4] = {}, accB[2][4][4] = {};

    auto load_stage = [&](int t) {
        const int k0 = t * 32;
        __half* As = Asm + (t & (NSTG-1))*ASZ;
        __half* Bs = Bsm + (t & (NSTG-1))*BSZ;
        #pragma unroll
        for (int cl = tid; cl < BM*4; cl += NT) {
            int m = cl >> 2, c = cl & 3;
            cp16(s2u(&As[m*32 + ((c ^ ((m>>1)&3)) << 3)]),
                 &A[(size_t)(m0 + m)*K + k0 + c*8]);
        }
        #pragma unroll
        for (int cl = tid; cl < 2*BN*4; cl += NT) {
            int n = cl >> 2, c = cl & 3;
            int gr = (n < BN) ? (n0 + n) : (D + n0 + (n - BN));
            cp16(s2u(&Bs[n*32 + ((c ^ ((n>>1)&3)) << 3)]),
                 &B[(size_t)gr*K + k0 + c*8]);
        }
        cp_commit();
    };

    auto compute = [&](int t) {
        const __half* As = Asm + (t & (NSTG-1))*ASZ;
        const __half* Bs = Bsm + (t & (NSTG-1))*BSZ;
        #pragma unroll
        for (int kk = 0; kk < 2; kk++) {
            unsigned af[2][4], bf1[2][4], bf2[2][4];
            #pragma unroll
            for (int i = 0; i < 2; i++)
                ldm4(af[i], &As[swzh(wm0 + i*16 + r15, kk*16 + khi)]);
            #pragma unroll
            for (int j = 0; j < 2; j++) {
                ldm4(bf1[j], &Bs[swzh(wn0 + j*16 + r15,      kk*16 + khi)]);
                ldm4(bf2[j], &Bs[swzh(BN + wn0 + j*16 + r15, kk*16 + khi)]);
            }
            #pragma unroll
            for (int i = 0; i < 2; i++)
                #pragma unroll
                for (int j = 0; j < 2; j++) {
                    mma16816(accA[i][2*j  ], af[i], bf1[j][0], bf1[j][2]);
                    mma16816(accA[i][2*j+1], af[i], bf1[j][1], bf1[j][3]);
                    mma16816(accB[i][2*j  ], af[i], bf2[j][0], bf2[j][2]);
                    mma16816(accB[i][2*j+1], af[i], bf2[j][1], bf2[j][3]);
                }
        }
    };

    const int NIT = K / 32;
    load_stage(0); load_stage(1); load_stage(2);
    for (int t = 0; t < NIT; t++) {
        if (t < NIT-2)       cp_wait<2>();
        else if (t == NIT-2) cp_wait<1>();
        else                 cp_wait<0>();
        __syncthreads();
        if (t + 3 < NIT) load_stage(t + 3);
        compute(t);
    }

    // ---- epilogue: GLU, half out ----
    #pragma unroll
    for (int i = 0; i < 2; i++) {
        int mA = m0 + wm0 + i*16 + g;
        #pragma unroll
        for (int jj = 0; jj < 4; jj++) {
            int col = n0 + wn0 + (jj >> 1)*16 + (jj & 1)*8 + 2*tg;
            float b10 = bias[col], b11 = bias[col+1];
            float b20 = bias[D+col], b21 = bias[D+col+1];
            float z10 = accA[i][jj][0] + b10, z11 = accA[i][jj][1] + b11;
            float z12 = accA[i][jj][2] + b10, z13 = accA[i][jj][3] + b11;
            float z20 = accB[i][jj][0] + b20, z21 = accB[i][jj][1] + b21;
            float z22 = accB[i][jj][2] + b20, z23 = accB[i][jj][3] + b21;
            float o0 = z10 * (1.0f/(1.0f+expf(-z20)));
            float o1 = z11 * (1.0f/(1.0f+expf(-z21)));
            float o2 = z12 * (1.0f/(1.0f+expf(-z22)));
            float o3 = z13 * (1.0f/(1.0f+expf(-z23)));
            *(__half2*)&O[(size_t)mA*D + col]     = __floats2half2_rn(o0, o1);
            *(__half2*)&O[(size_t)(mA+8)*D + col] = __floats2half2_rn(o2, o3);
        }
    }
}

// ---------------- layernorm: one warp per row ------------------------------
__global__ __launch_bounds__(256) void ln_k(const float* __restrict__ x,
    const float* __restrict__ g, const float* __restrict__ b, __half* __restrict__ y)
{
    int warp = threadIdx.x >> 5, lane = threadIdx.x & 31;
    int s = blockIdx.x*8 + warp;
    const float* row = x + (size_t)s*D + lane*24;
    float v[24];
    #pragma unroll
    for (int j = 0; j < 6; j++) {
        float4 t = *(const float4*)(row + j*4);
        v[4*j] = t.x; v[4*j+1] = t.y; v[4*j+2] = t.z; v[4*j+3] = t.w;
    }
    float sum = 0.0f;
    #pragma unroll
    for (int i = 0; i < 24; i++) sum += v[i];
    #pragma unroll
    for (int o = 16; o > 0; o >>= 1) sum += __shfl_xor_sync(0xffffffffu, sum, o);
    float mean = sum * (1.0f/768.0f);
    float vs = 0.0f;
    #pragma unroll
    for (int i = 0; i < 24; i++) { float d = v[i] - mean; vs += d*d; }
    #pragma unroll
    for (int o = 16; o > 0; o >>= 1) vs += __shfl_xor_sync(0xffffffffu, vs, o);
    float inv = rsqrtf(vs * (1.0f/768.0f) + 1e-5f);
    const float* gp = g + lane*24;
    const float* bp = b + lane*24;
    __half hb[24];
    #pragma unroll
    for (int j = 0; j < 6; j++) {
        float4 gg = *(const float4*)(gp + j*4);
        float4 bb = *(const float4*)(bp + j*4);
        hb[4*j  ] = __float2half_rn((v[4*j  ]-mean)*inv*gg.x + bb.x);
        hb[4*j+1] = __float2half_rn((v[4*j+1]-mean)*inv*gg.y + bb.y);
        hb[4*j+2] = __float2half_rn((v[4*j+2]-mean)*inv*gg.z + bb.z);
        hb[4*j+3] = __float2half_rn((v[4*j+3]-mean)*inv*gg.w + bb.w);
    }
    __half* orow = y + (size_t)s*D + lane*24;
    #pragma unroll
    for (int j = 0; j < 3; j++)
        *(uint4*)&orow[8*j] = *(uint4*)&hb[8*j];
}

// ---------------- position scan (chunked 3-pass) ---------------------------
__global__ __launch_bounds__(256) void ps1_k(const float* __restrict__ h,
    float* __restrict__ psum, float* __restrict__ plse)
{
    int d = blockIdx.x*256 + threadIdx.x;
    int c = blockIdx.y;
    float acc = 0.0f, lse = -__int_as_float(0x7f800000);
    for (int t = 0; t < 32; t++) {
        int s = c*32 + t;
        float hv = h[(size_t)s*(2*D) + d];
        float lg = h[(size_t)s*(2*D) + D + d];
        float lc = (hv >= 0.0f) ? (-log1pf(expf(-hv))) : (hv - log1pf(expf(hv)));
        acc += lc;
        lse = logaddexpf(lse, lg - acc);
    }
    psum[c*D + d] = acc;
    plse[c*D + d] = lse;
}
__global__ __launch_bounds__(256) void ps2_k(const float* __restrict__ psum,
    const float* __restrict__ plse, float* __restrict__ accb, float* __restrict__ Rarr)
{
    int d = blockIdx.x*256 + threadIdx.x;
    float ab = 0.0f, R = 0.0f;
    for (int c = 0; c < NCH; c++) {
        accb[c*D + d] = ab;
        Rarr[c*D + d] = R;
        R = logaddexpf(R, plse[c*D + d] - ab);
        ab += psum[c*D + d];
    }
}
__global__ __launch_bounds__(256) void ps3_k(const float* __restrict__ h,
    const float* __restrict__ accb, const float* __restrict__ Rarr,
    float* __restrict__ x)
{
    int d = blockIdx.x*256 + threadIdx.x;
    int c = blockIdx.y;
    float ab = accb[c*D + d], R = Rarr[c*D + d];
    float acc = 0.0f, lse = -__int_as_float(0x7f800000);
    for (int t = 0; t < 32; t++) {
        int s = c*32 + t;
        float hv = h[(size_t)s*(2*D) + d];
        float lg = h[(size_t)s*(2*D) + D + d];
        float lc = (hv >= 0.0f) ? (-log1pf(expf(-hv))) : (hv - log1pf(expf(hv)));
        acc += lc;
        lse = logaddexpf(lse, lg - acc);
        float out = (ab + acc) + logaddexpf(R, lse - ab);
        x[(size_t)s*D + d] += out;
    }
}

// ---------------- attention pass A: per-chunk sums -------------------------
__global__ __launch_bounds__(1024) void attnA_k(const float* __restrict__ qkv,
    float* __restrict__ Asum, float* __restrict__ Zsum)
{
    int c = blockIdx.x, hh = blockIdx.y;
    int tid = threadIdx.x, lane = tid & 31, wid = tid >> 5;
    __shared__ float ek[CT][33], ev[CT][33];
    const float* base = qkv + (size_t)(c*CT + wid)*QKV_N + hh*96;
    ek[wid][lane] = expf(base[32 + lane]);
    ev[wid][lane] = expf(base[64 + lane]);
    __syncthreads();
    float m = 0.0f;
    #pragma unroll
    for (int t = 0; t < CT; t++) m = fmaf(ek[t][wid], ev[t][lane], m);
    Asum[(size_t)(((hh*NCH)+c)*DKV + wid)*DKV + lane] = m;
    if (wid == 0) {
        float z = 0.0f;
        #pragma unroll
        for (int t = 0; t < CT; t++) z += ek[t][lane];
        Zsum[(size_t)((hh*NCH)+c)*DKV + lane] = z;
    }
}

// ---------------- attention pass B: exclusive prefix over chunks -----------
__global__ __launch_bounds__(1024) void attnB_k(const float* __restrict__ Asum,
    const float* __restrict__ Zsum, float* __restrict__ Mcar, float* __restrict__ Zcar)
{
    int hh = blockIdx.x;
    int tid = threadIdx.x, lane = tid & 31, wid = tid >> 5;
    float run = 0.0f;
    for (int c = 0; c < NCH; c++) {
        size_t idx = (size_t)(((hh*NCH)+c)*DKV + wid)*DKV + lane;
        Mcar[idx] = run;
        run += Asum[idx];
    }
    if (wid == 0) {
        float rz = 0.0f;
        for (int c = 0; c < NCH; c++) {
            size_t iz = (size_t)((hh*NCH)+c)*DKV + lane;
            Zcar[iz] = rz;
            rz += Zsum[iz];
        }
    }
}

// ---------------- attention pass C: carry + intra-chunk --------------------
__global__ __launch_bounds__(1024) void attnC_k(const float* __restrict__ qkv,
    const float* __restrict__ Mcar, const float* __restrict__ Zcar,
    __half* __restrict__ att)
{
    int c = blockIdx.x, hh = blockIdx.y;
    int tid = threadIdx.x, lane = tid & 31, wid = tid >> 5;
    __shared__ float eq[CT][33], ek[CT][33], ev[CT][33], P[CT][33], M0[DKV][33];
    __shared__ float z0[DKV];
    const float* base = qkv + (size_t)(c*CT + wid)*QKV_N + hh*96;
    eq[wid][lane] = expf(base[      lane]);
    ek[wid][lane] = expf(base[32 +  lane]);
    ev[wid][lane] = expf(base[64 +  lane]);
    M0[wid][lane] = Mcar[(size_t)(((hh*NCH)+c)*DKV + wid)*DKV + lane];
    if (tid < DKV) z0[tid] = Zcar[(size_t)((hh*NCH)+c)*DKV + tid];
    __syncthreads();
    float p = 0.0f;
    #pragma unroll
    for (int k = 0; k < DKV; k++) p = fmaf(eq[wid][k], ek[lane][k], p);
    P[wid][lane] = p;
    __syncthreads();
    float num = 0.0f, den = 0.0f;
    #pragma unroll
    for (int k = 0; k < DKV; k++) {
        float q = eq[wid][k];
        num = fmaf(q, M0[k][lane], num);
        den = fmaf(q, z0[k], den);
    }
    for (int s2 = 0; s2 <= wid; s2++) {
        float ps = P[wid][s2];
        num = fmaf(ps, ev[s2][lane], num);
        den += ps;
    }
    att[(size_t)(c*CT + wid)*D + hh*DKV + lane] = __float2half_rn(logf(num) - logf(den));
}

// ---------------- launcher -----------------------------------------------
extern "C" void kernel_launch(void* const* d_in, const int* in_sizes, int n_in,
                              void* d_out, int out_size)
{
    const int*   tok  = (const int*)  d_in[0];
    const float* embw = (const float*)d_in[1];
    const float* posw = (const float*)d_in[2];
    const float* posb = (const float*)d_in[3];
    const float* ln1g = (const float*)d_in[4];
    const float* ln1b = (const float*)d_in[5];
    const float* qkvw = (const float*)d_in[6];
    const float* qkvb = (const float*)d_in[7];
    const float* ffw1 = (const float*)d_in[8];
    const float* ffb1 = (const float*)d_in[9];
    const float* ffw2 = (const float*)d_in[10];
    const float* lnfg = (const float*)d_in[11];
    const float* lnfb = (const float*)d_in[12];
    float* out = (float*)d_out;

    float *x,*hh,*qkv,*Asum,*Zsum,*Mcar,*Zcar,*psum,*plse,*paccb,*pR;
    __half *xh,*xnh,*atth,*gluh,*poswh,*qkvwh,*ff1wh,*ff2wh,*embwh;
    cudaGetSymbolAddress((void**)&x,    g_x);
    cudaGetSymbolAddress((void**)&hh,   g_h);
    cudaGetSymbolAddress((void**)&qkv,  g_qkv);
    cudaGetSymbolAddress((void**)&Asum, g_Asum);
    cudaGetSymbolAddress((void**)&Zsum, g_Zsum);
    cudaGetSymbolAddress((void**)&Mcar, g_Mcar);
    cudaGetSymbolAddress((void**)&Zcar, g_Zcar);
    cudaGetSymbolAddress((void**)&psum, g_ps_sum);
    cudaGetSymbolAddress((void**)&plse, g_ps_lse);
    cudaGetSymbolAddress((void**)&paccb,g_ps_accb);
    cudaGetSymbolAddress((void**)&pR,   g_ps_R);
    cudaGetSymbolAddress((void**)&xh,    g_xh);
    cudaGetSymbolAddress((void**)&xnh,   g_xnh);
    cudaGetSymbolAddress((void**)&atth,  g_atth);
    cudaGetSymbolAddress((void**)&gluh,  g_gluh);
    cudaGetSymbolAddress((void**)&poswh, g_poswh);
    cudaGetSymbolAddress((void**)&qkvwh, g_qkvwh);
    cudaGetSymbolAddress((void**)&ff1wh, g_ff1wh);
    cudaGetSymbolAddress((void**)&ff2wh, g_ff2wh);
    cudaGetSymbolAddress((void**)&embwh, g_embwh);

    // smem per config: NSTG*(BM+BN)*32 halfs
    const int sm_A = NSTG*( 64+128)*32*2;   // 49152  (64x128, pos/qkv)
    const int sm_B = NSTG*( 64+ 64)*32*2;   // 32768  (64x64,  ff2)
    const int sm_C = NSTG*(128+128)*32*2;   // 65536  (128x128, logits)
    const int sm_G = NSTG*( 64+128)*32*2;   // 49152  (ff1+glu dual 64-panel)
    cudaFuncSetAttribute(hgemm<2,4,2,2>, cudaFuncAttributeMaxDynamicSharedMemorySize, sm_A);
    cudaFuncSetAttribute(hgemm<2,2,2,2>, cudaFuncAttributeMaxDynamicSharedMemorySize, sm_B);
    cudaFuncSetAttribute(hgemm<2,4,4,2>, cudaFuncAttributeMaxDynamicSharedMemorySize, sm_C);
    cudaFuncSetAttribute(hgemm_glu,      cudaFuncAttributeMaxDynamicSharedMemorySize, sm_G);

    // ---- weight prep (every call; deterministic) ----
    tconv_k<<<dim3(2*D/32,  D/64, 1     ), dim3(32,8)>>>(posw, poswh, D, 2*D);
    tconv_k<<<dim3(QKV_N/32,D/64, LAYERS), dim3(32,8)>>>(qkvw, qkvwh, D, QKV_N);
    tconv_k<<<dim3(FF_N/32, D/64, LAYERS), dim3(32,8)>>>(ffw1, ff1wh, D, FF_N);
    tconv_k<<<dim3(D/32,    D/64, LAYERS), dim3(32,8)>>>(ffw2, ff2wh, D, D);
    conv_k<<<1024, 256>>>(embw, embwh, (size_t)VSZ*D/4);

    // ---- embed + position recurrence ----
    embed_k<<<S, 256>>>(tok, embw, x, xh);
    hgemm<2,4,2,2><<<dim3(S/64, 2*D/128), 256, sm_A>>>(
        xh, poswh, posb, nullptr, hh, S, 2*D, D);
    ps1_k<<<dim3(3, NCH), 256>>>(hh, psum, plse);
    ps2_k<<<3, 256>>>(psum, plse, paccb, pR);
    ps3_k<<<dim3(3, NCH), 256>>>(hh, paccb, pR, x);

    for (int l = 0; l < LAYERS; l++) {
        ln_k<<<S/8, 256>>>(x, ln1g + (size_t)l*D, ln1b + (size_t)l*D, xnh);
        hgemm<2,4,2,2><<<dim3(S/64, QKV_N/128), 256, sm_A>>>(
            xnh, qkvwh + (size_t)l*D*QKV_N, qkvb + (size_t)l*QKV_N, nullptr, qkv, S, QKV_N, D);
        attnA_k<<<dim3(NCH, HEADS), 1024>>>(qkv, Asum, Zsum);
        attnB_k<<<HEADS, 1024>>>(Asum, Zsum, Mcar, Zcar);
        attnC_k<<<dim3(NCH, HEADS), 1024>>>(qkv, Mcar, Zcar, atth);
        hgemm_glu<<<dim3(S/64, D/64), 128, sm_G>>>(
            atth, ff1wh + (size_t)l*D*FF_N, ffb1 + (size_t)l*FF_N, gluh, D);
        hgemm<2,2,2,2><<<dim3(S/64, D/64), 128, sm_B>>>(
            gluh, ff2wh + (size_t)l*D*D, nullptr, x, x, S, D, D);
    }

    ln_k<<<S/8, 256>>>(x, lnfg, lnfb, xnh);
    hgemm<2,4,4,2><<<dim3(S/128, VSZ/128), 256, sm_C>>>(
        xnh, embwh, nullptr, nullptr, out, S, VSZ, D);
}